// round 11
// baseline (speedup 1.0000x reference)
#include <cuda_runtime.h>
#include <cuda_fp16.h>
#include <cstdint>

#define BATCH 8
#define CH    128
#define HH    48
#define WW    64
#define NN    (HH*WW)   // 3072

#define S2F ((float)(1.4426950408889634 * 0.088388347648318447))

__device__ __half g_f0h[BATCH*NN*CH];
__device__ __half g_f1h[BATCH*NN*CH];
__device__ __half g_qh [BATCH*NN*CH];
__device__ __half g_kh [BATCH*NN*CH];
__device__ int    g_done[BATCH];       // stage0 completions per batch (target 48)

__device__ __forceinline__ uint32_t smem_u32(const void* p) {
    uint32_t a;
    asm("{ .reg .u64 t; cvta.to.shared.u64 t, %1; cvt.u32.u64 %0, t; }" : "=r"(a) : "l"(p));
    return a;
}
__device__ __forceinline__ void ldsm4(uint32_t* r, uint32_t addr) {
    asm volatile("ldmatrix.sync.aligned.m8n8.x4.shared.b16 {%0,%1,%2,%3}, [%4];"
        : "=r"(r[0]), "=r"(r[1]), "=r"(r[2]), "=r"(r[3]) : "r"(addr));
}
__device__ __forceinline__ void mma16816(float* c, const uint32_t* a, const uint32_t* b) {
    asm volatile("mma.sync.aligned.m16n8k16.row.col.f32.f16.f16.f32 "
        "{%0,%1,%2,%3}, {%4,%5,%6,%7}, {%8,%9}, {%0,%1,%2,%3};"
        : "+f"(c[0]), "+f"(c[1]), "+f"(c[2]), "+f"(c[3])
        : "r"(a[0]), "r"(a[1]), "r"(a[2]), "r"(a[3]), "r"(b[0]), "r"(b[1]));
}
__device__ __forceinline__ float ex2f(float x) {
    float y; asm("ex2.approx.f32 %0, %1;" : "=f"(y) : "f"(x)); return y;
}
#define CP16(dst, src) asm volatile("cp.async.cg.shared.global [%0], [%1], 16;" :: "r"(dst), "l"(src))
#define CP_COMMIT()    asm volatile("cp.async.commit_group;" ::: "memory")
#define CP_WAIT0()     asm volatile("cp.async.wait_group 0;" ::: "memory")
#define GBAR(id)       asm volatile("bar.sync %0, 128;" :: "r"(id) : "memory")

#define RS 136

// Flash smem: 128-query A tile + per-group double-buffered 64-key B half-tiles
#define FSM_A    0                     // 128*RS*2 = 34816
#define FSM_B    34816                 // 4 x 17408  (group g, buf c at (g*2+c))
#define FSM_V    104448                // 4 x 512
#define FSM_RED  106496                // 384 floats
#define FSM_TOT  108032

// Proj smem map (fits inside FSM_TOT)
#define PSM_F   0
#define PSM_W   34816
#define PSM_QB  69632
#define PSM_KB  70144

// 64-row half-tile prefetch by one 128-thread group (tl = t & 127)
__device__ __forceinline__ void prefetch_half(uint32_t dstBase, const __half* src, int tl) {
    #pragma unroll
    for (int it = 0; it < 8; it++) {
        int idx = it * 128 + tl;
        int r = idx >> 4, g = idx & 15;
        CP16(dstBase + (uint32_t)((r * RS + g * 8) * 2), src + (size_t)r * CH + g * 8);
    }
}

// ---------------------------------------------------------------------------
// Flash body: 128-query tile, 24 key tiles of 128 keys.
// 8 warps = 4 query-blocks (wq, 32 rows each) x 2 key-half groups (wc).
// Each group owns its own double-buffered 64-key half-tile + named barrier
// (independent pipelines, anti-phased). Warp tile 32q x 64k: each B fragment
// feeds 4 HMMA (2 query row-blocks), cutting smem reads 25% per unit work.
// Scores pre-scaled (S2 folded into B operand) -> p = ex2(score).
// ---------------------------------------------------------------------------
template<int MODE>
__device__ __forceinline__ void flash_body(
    const __half* __restrict__ A, const __half* __restrict__ Bm,
    const float* __restrict__ vsrc, float* __restrict__ out,
    int b, int n0, char* smem)
{
    const uint32_t sb = smem_u32(smem);
    const int t = threadIdx.x, wid = t >> 5, lane = t & 31;
    const int wc = wid >> 2, wq = wid & 3;   // key-half group / query block
    const int tl = t & 127;                  // lane within group
    const size_t vbase = (size_t)b * 2 * NN;

    {   // query tile: 128 rows (all 256 threads)
        __half* sA = (__half*)smem;
        const __half* src = A + ((size_t)b * NN + n0) * CH;
        #pragma unroll
        for (int it = 0; it < 8; it++) {
            int idx = it * 256 + t;
            int r = idx >> 4, g = idx & 15;
            *(uint4*)(sA + r * RS + g * 8) = *(const uint4*)(src + (size_t)r * CH + g * 8);
        }
    }

    // Group wc's source rows for tile T start at T*128 + wc*64
    const __half* Bg = Bm + ((size_t)b * NN + wc * 64) * CH;
    const uint32_t bBuf0 = sb + FSM_B + (uint32_t)(wc * 2) * 17408;
    const uint32_t bBuf1 = bBuf0 + 17408;
    const uint32_t vBuf0 = sb + FSM_V + (uint32_t)(wc * 2) * 512;
    const uint32_t vBuf1 = vBuf0 + 512;

    prefetch_half(bBuf0, Bg, tl);
    if (MODE == 1 && tl < 32) {
        const float* s = (tl < 16) ? (vsrc + vbase + wc * 64 + tl * 4)
                                   : (vsrc + vbase + NN + wc * 64 + (tl - 16) * 4);
        CP16(vBuf0 + ((tl < 16) ? tl * 16 : 256 + (tl - 16) * 16), s);
    }
    CP_COMMIT();

    const int g8 = (lane >> 3) & 1, g16 = lane >> 4, l7 = lane & 7, tid4 = lane & 3;
    // Two A row-block ldsm bases (rows wq*32 and wq*32+16)
    const uint32_t aB0 = sb + FSM_A + (uint32_t)(((wq * 32 + l7 + g8 * 8) * RS + g16 * 8) * 2);
    const uint32_t aB1 = aB0 + (uint32_t)(16 * RS * 2);
    const uint32_t bOff = (uint32_t)(((l7 + g16 * 8) * RS + g8 * 8) * 2);

    // Tile-0 halves + sA ready (block-wide once)
    CP_WAIT0();
    __syncthreads();

    // Prefetch tile 1 into buf1 (per group)
    prefetch_half(bBuf1, Bg + (size_t)128 * CH, tl);
    if (MODE == 1 && tl < 32) {
        const float* s = (tl < 16) ? (vsrc + vbase + 128 + wc * 64 + tl * 4)
                                   : (vsrc + vbase + NN + 128 + wc * 64 + (tl - 16) * 4);
        CP16(vBuf1 + ((tl < 16) ? tl * 16 : 256 + (tl - 16) * 16), s);
    }
    CP_COMMIT();

    float L[2][2], AX[2][2], AY[2][2];
    #pragma unroll
    for (int rb = 0; rb < 2; rb++)
        #pragma unroll
        for (int h = 0; h < 2; h++) { L[rb][h] = 0.f; AX[rb][h] = 0.f; AY[rb][h] = 0.f; }

    for (int tile = 0; tile < NN / 128; tile++) {
        const uint32_t cur = tile & 1;
        if (tile > 0) {
            CP_WAIT0();                    // this tile's half ready
            GBAR(1 + wc);                  // group done reading buf being refilled
            if (tile + 1 < NN / 128) {
                const int mn = (tile + 1) * 128;
                prefetch_half(cur ? bBuf0 : bBuf1, Bg + (size_t)mn * CH, tl);
                if (MODE == 1 && tl < 32) {
                    const float* s = (tl < 16)
                        ? (vsrc + vbase + mn + wc * 64 + tl * 4)
                        : (vsrc + vbase + NN + mn + wc * 64 + (tl - 16) * 4);
                    CP16((cur ? vBuf0 : vBuf1)
                         + ((tl < 16) ? tl * 16 : 256 + (tl - 16) * 16), s);
                }
                CP_COMMIT();
            }
        }

        const uint32_t bB = (cur ? bBuf1 : bBuf0) + bOff;
        const float* sV = (const float*)(smem + ((cur ? vBuf1 : vBuf0) - sb));

        float c[2][8][4];
        #pragma unroll
        for (int rb = 0; rb < 2; rb++)
            #pragma unroll
            for (int j = 0; j < 8; j++)
                #pragma unroll
                for (int q = 0; q < 4; q++) c[rb][j][q] = 0.f;

        #pragma unroll
        for (int k = 0; k < 8; k++) {
            uint32_t a0[4], a1[4];
            ldsm4(a0, aB0 + k * 32);
            ldsm4(a1, aB1 + k * 32);
            #pragma unroll
            for (int j2 = 0; j2 < 4; j2++) {
                uint32_t bb[4];
                ldsm4(bb, bB + j2 * (16 * RS * 2) + k * 32);
                mma16816(c[0][2 * j2],     a0, bb);
                mma16816(c[0][2 * j2 + 1], a0, bb + 2);
                mma16816(c[1][2 * j2],     a1, bb);
                mma16816(c[1][2 * j2 + 1], a1, bb + 2);
            }
        }

        #pragma unroll
        for (int rb = 0; rb < 2; rb++) {
            float Lt0 = 0.f, Lt1 = 0.f;
            #pragma unroll
            for (int j = 0; j < 8; j++) {
                float p0 = ex2f(c[rb][j][0]);
                float p1 = ex2f(c[rb][j][1]);
                float p2 = ex2f(c[rb][j][2]);
                float p3 = ex2f(c[rb][j][3]);
                if (MODE == 0) {
                    float vx0 = (float)(j * 8 + tid4 * 2);   // m & 63
                    float vx1 = vx0 + 1.f;
                    Lt0 += p0 + p1;  Lt1 += p2 + p3;
                    AX[rb][0] += p0 * vx0 + p1 * vx1;
                    AX[rb][1] += p2 * vx0 + p3 * vx1;
                } else {
                    int cl = j * 8 + tid4 * 2;               // local within half
                    float2 x2 = *(const float2*)&sV[cl];
                    float2 y2 = *(const float2*)&sV[64 + cl];
                    L[rb][0]  += p0 + p1;          L[rb][1]  += p2 + p3;
                    AX[rb][0] += p0 * x2.x + p1 * x2.y;
                    AX[rb][1] += p2 * x2.x + p3 * x2.y;
                    AY[rb][0] += p0 * y2.x + p1 * y2.y;
                    AY[rb][1] += p2 * y2.x + p3 * y2.y;
                }
            }
            if (MODE == 0) {
                float vy = (float)(2 * tile + wc);           // m >> 6
                L[rb][0] += Lt0;  L[rb][1] += Lt1;
                AY[rb][0] += vy * Lt0;  AY[rb][1] += vy * Lt1;
            }
        }
    }

    #pragma unroll
    for (int o = 1; o <= 2; o <<= 1)
        #pragma unroll
        for (int rb = 0; rb < 2; rb++)
            #pragma unroll
            for (int h = 0; h < 2; h++) {
                L[rb][h]  += __shfl_xor_sync(0xffffffffu, L[rb][h],  o);
                AX[rb][h] += __shfl_xor_sync(0xffffffffu, AX[rb][h], o);
                AY[rb][h] += __shfl_xor_sync(0xffffffffu, AY[rb][h], o);
            }

    // Cross-group reduction (block-wide: both groups have left the loop)
    float* red = (float*)(smem + FSM_RED);
    __syncthreads();
    if (wc == 1 && tid4 == 0) {
        #pragma unroll
        for (int rb = 0; rb < 2; rb++)
            #pragma unroll
            for (int h = 0; h < 2; h++) {
                int rl = wq * 32 + rb * 16 + h * 8 + (lane >> 2);
                red[rl]       = L[rb][h];
                red[128 + rl] = AX[rb][h];
                red[256 + rl] = AY[rb][h];
            }
    }
    __syncthreads();
    if (wc == 0 && tid4 == 0) {
        float* ob = out + vbase;
        #pragma unroll
        for (int rb = 0; rb < 2; rb++)
            #pragma unroll
            for (int h = 0; h < 2; h++) {
                int rl = wq * 32 + rb * 16 + h * 8 + (lane >> 2);
                float Lt  = L[rb][h]  + red[rl];
                float AXt = AX[rb][h] + red[128 + rl];
                float AYt = AY[rb][h] + red[256 + rl];
                int n = n0 + rl;
                float fx = AXt / Lt, fy = AYt / Lt;
                if (MODE == 0) { fx -= (float)(n & (WW - 1)); fy -= (float)(n >> 6); }
                ob[n] = fx;  ob[NN + n] = fy;
            }
    }
}

// ---------------------------------------------------------------------------
// Proj body (unchanged R8): 128-row tile; q kept in regs as GEMM2 A-fragments.
// ---------------------------------------------------------------------------
__device__ __forceinline__ void proj_body(
    const __half* __restrict__ F0, const float* __restrict__ qw,
    const float* __restrict__ qb,  const float* __restrict__ kw,
    const float* __restrict__ kb,
    __half* __restrict__ QH, __half* __restrict__ KH,
    int b, int n0, char* smem)
{
    __half* sF = (__half*)(smem + PSM_F);
    __half* sW = (__half*)(smem + PSM_W);
    float* qbS = (float*)(smem + PSM_QB);
    float* kbS = (float*)(smem + PSM_KB);
    const uint32_t sbF = smem_u32(sF), sbW = smem_u32(sW);

    const int t = threadIdx.x, wid = t >> 5, lane = t & 31;

    {
        const __half* src = F0 + ((size_t)b * NN + n0) * CH;
        #pragma unroll
        for (int it = 0; it < 8; it++) {
            int idx = it * 256 + t;
            int r = idx >> 4, g = idx & 15;
            *(uint4*)(sF + r * RS + g * 8) = *(const uint4*)(src + (size_t)r * CH + g * 8);
        }
    }
    #pragma unroll
    for (int it = 0; it < 16; it++) {
        int idx = it * 256 + t;
        int r = idx >> 5, g = idx & 31;
        float4 w = *(const float4*)(qw + (size_t)r * CH + g * 4);
        __half h[4] = {__float2half(w.x), __float2half(w.y), __float2half(w.z), __float2half(w.w)};
        *(uint2*)(sW + r * RS + g * 4) = *(uint2*)h;
    }
    if (t < 128) { qbS[t] = qb[t]; kbS[t] = kb[t]; }
    __syncthreads();

    const int g8 = (lane >> 3) & 1, g16 = lane >> 4, l7 = lane & 7, tid4 = lane & 3;
    const uint32_t aBase = sbF + (uint32_t)(((wid * 16 + l7 + g8 * 8) * RS + g16 * 8) * 2);
    const uint32_t bBase = sbW + (uint32_t)(((l7 + g16 * 8) * RS + g8 * 8) * 2);

    float c[16][4];
    #pragma unroll
    for (int j = 0; j < 16; j++)
        #pragma unroll
        for (int q = 0; q < 4; q++) c[j][q] = 0.f;
    #pragma unroll
    for (int k = 0; k < 8; k++) {
        uint32_t a[4];
        ldsm4(a, aBase + k * 32);
        #pragma unroll
        for (int j2 = 0; j2 < 8; j2++) {
            uint32_t bb[4];
            ldsm4(bb, bBase + j2 * (16 * RS * 2) + k * 32);
            mma16816(c[2 * j2],     a, bb);
            mma16816(c[2 * j2 + 1], a, bb + 2);
        }
    }

    uint32_t hq[16][2];
    const int r0 = wid * 16 + (lane >> 2);
    #pragma unroll
    for (int j = 0; j < 16; j++) {
        int col = j * 8 + tid4 * 2;
        float b0 = qbS[col], b1 = qbS[col + 1];
        __half2 v0 = __floats2half2_rn(c[j][0] + b0, c[j][1] + b1);
        __half2 v1 = __floats2half2_rn(c[j][2] + b0, c[j][3] + b1);
        hq[j][0] = *(uint32_t*)&v0;
        hq[j][1] = *(uint32_t*)&v1;
        *(uint32_t*)(QH + ((size_t)b * NN + n0 + r0) * CH + col)     = hq[j][0];
        *(uint32_t*)(QH + ((size_t)b * NN + n0 + r0 + 8) * CH + col) = hq[j][1];
    }

    __syncthreads();
    #pragma unroll
    for (int it = 0; it < 16; it++) {
        int idx = it * 256 + t;
        int r = idx >> 5, g = idx & 31;
        float4 w = *(const float4*)(kw + (size_t)r * CH + g * 4);
        __half h[4] = {__float2half(w.x), __float2half(w.y), __float2half(w.z), __float2half(w.w)};
        *(uint2*)(sW + r * RS + g * 4) = *(uint2*)h;
    }
    __syncthreads();

    float c2[16][4];
    #pragma unroll
    for (int j = 0; j < 16; j++)
        #pragma unroll
        for (int q = 0; q < 4; q++) c2[j][q] = 0.f;
    #pragma unroll
    for (int kk = 0; kk < 8; kk++) {
        uint32_t a[4] = { hq[2 * kk][0], hq[2 * kk][1], hq[2 * kk + 1][0], hq[2 * kk + 1][1] };
        #pragma unroll
        for (int j2 = 0; j2 < 8; j2++) {
            uint32_t bb[4];
            ldsm4(bb, bBase + j2 * (16 * RS * 2) + kk * 32);
            mma16816(c2[2 * j2],     a, bb);
            mma16816(c2[2 * j2 + 1], a, bb + 2);
        }
    }
    #pragma unroll
    for (int j = 0; j < 16; j++) {
        int col = j * 8 + tid4 * 2;
        float b0 = kbS[col], b1 = kbS[col + 1];
        __half2 v0 = __floats2half2_rn((c2[j][0] + b0) * S2F, (c2[j][1] + b1) * S2F);
        __half2 v1 = __floats2half2_rn((c2[j][2] + b0) * S2F, (c2[j][3] + b1) * S2F);
        *(uint32_t*)(KH + ((size_t)b * NN + n0 + r0) * CH + col)     = *(uint32_t*)&v0;
        *(uint32_t*)(KH + ((size_t)b * NN + n0 + r0 + 8) * CH + col) = *(uint32_t*)&v1;
    }
}

// ---------------------------------------------------------------------------
// Fused pipeline kernel: 576 CTAs in bid order:
//   bid   0..191 : proj   (b = idx/24, n0 = (idx%24)*128)  -> g_done[b] += 1
//   bid 192..383 : flash0 (b = idx/24, n0 = (idx%24)*128)  -> g_done[b] += 1
//   bid 384..575 : flash1 — spins until g_done[b] == 48 (24 proj + 24 flash0).
// g_done[] is zeroed by the conv kernel preceding this launch.
// ---------------------------------------------------------------------------
__global__ void __launch_bounds__(256, 2) fused_kernel(
    const __half* __restrict__ f0h, const __half* __restrict__ f1h,
    const float* __restrict__ qw, const float* __restrict__ qb,
    const float* __restrict__ kw, const float* __restrict__ kb,
    __half* __restrict__ qh, __half* __restrict__ kh,
    float* __restrict__ flow_pred, float* __restrict__ flow)
{
    extern __shared__ char smem[];
    const int bid = blockIdx.x;

    if (bid < 192) {
        const int idx = bid, b = idx / 24;
        proj_body(f0h, qw, qb, kw, kb, qh, kh, b, (idx % 24) * 128, smem);
        __threadfence();
        __syncthreads();
        if (threadIdx.x == 0) atomicAdd(&g_done[b], 1);
    } else if (bid < 384) {
        const int idx = bid - 192, b = idx / 24;
        flash_body<0>(f0h, f1h, nullptr, flow_pred, b, (idx % 24) * 128, smem);
        __threadfence();
        __syncthreads();
        if (threadIdx.x == 0) atomicAdd(&g_done[b], 1);
    } else {
        const int idx = bid - 384, b = idx / 24;
        if (threadIdx.x == 0) {
            while (atomicAdd(&g_done[b], 0) < 48) __nanosleep(200);
            __threadfence();
        }
        __syncthreads();
        flash_body<1>(qh, kh, flow_pred, flow, b, (idx % 24) * 128, smem);
    }
}

// ---------------------------------------------------------------------------
// Fused transpose+convert (re-zeroes g_done): z<8 f0->f0h (x1), z>=8 f1 (xS2)
// ---------------------------------------------------------------------------
__global__ void __launch_bounds__(256) convH2_kernel(
    const float* __restrict__ f0, const float* __restrict__ f1,
    __half* __restrict__ o0, __half* __restrict__ o1)
{
    __shared__ float tile[32][33];
    if (blockIdx.x == 0 && blockIdx.y == 0 && blockIdx.z == 0 &&
        threadIdx.x < BATCH && threadIdx.y == 0)
        g_done[threadIdx.x] = 0;

    const int z = blockIdx.z, b = z & 7;
    const float* in = (z < 8) ? f0 : f1;
    __half* out = (z < 8) ? o0 : o1;
    const float scale = (z < 8) ? 1.0f : S2F;
    const int n0 = blockIdx.x * 32, c0 = blockIdx.y * 32;
    const int tx = threadIdx.x, ty = threadIdx.y;

    const float* ip = in + ((size_t)b * CH + c0) * NN + n0;
    #pragma unroll
    for (int i = 0; i < 4; i++) {
        int c = ty + i * 8;
        tile[c][tx] = ip[(size_t)c * NN + tx];
    }
    __syncthreads();
    __half* op = out + ((size_t)b * NN + n0) * CH + c0;
    #pragma unroll
    for (int i = 0; i < 4; i++) {
        int nr = ty + i * 8;
        op[(size_t)nr * CH + tx] = __float2half(tile[tx][nr] * scale);
    }
}

extern "C" void kernel_launch(void* const* d_in, const int* in_sizes, int n_in,
                              void* d_out, int out_size)
{
    const float* f0 = (const float*)d_in[0];
    const float* f1 = (const float*)d_in[1];
    const float* qw = (const float*)d_in[2];
    const float* qb = (const float*)d_in[3];
    const float* kw = (const float*)d_in[4];
    const float* kb = (const float*)d_in[5];

    float* out       = (float*)d_out;
    float* flow      = out;
    float* flow_pred = out + (size_t)BATCH * 2 * NN;

    void* p;
    cudaGetSymbolAddress(&p, g_f0h); __half* f0h = (__half*)p;
    cudaGetSymbolAddress(&p, g_f1h); __half* f1h = (__half*)p;
    cudaGetSymbolAddress(&p, g_qh);  __half* qh  = (__half*)p;
    cudaGetSymbolAddress(&p, g_kh);  __half* kh  = (__half*)p;

    cudaFuncSetAttribute(fused_kernel, cudaFuncAttributeMaxDynamicSharedMemorySize, FSM_TOT);

    dim3 cgrid(NN / 32, CH / 32, 2 * BATCH);
    dim3 cblk(32, 8);

    convH2_kernel<<<cgrid, cblk>>>(f0, f1, f0h, f1h);
    fused_kernel<<<576, 256, FSM_TOT>>>(f0h, f1h, qw, qb, kw, kb, qh, kh,
                                        flow_pred, flow);
}

// round 12
// speedup vs baseline: 1.0500x; 1.0500x over previous
#include <cuda_runtime.h>
#include <cuda_fp16.h>
#include <cstdint>

#define BATCH 8
#define CH    128
#define HH    48
#define WW    64
#define NN    (HH*WW)   // 3072

#define S2F ((float)(1.4426950408889634 * 0.088388347648318447))

__device__ __half g_f0h[BATCH*NN*CH];
__device__ __half g_f1h[BATCH*NN*CH];
__device__ __half g_qh [BATCH*NN*CH];
__device__ __half g_kh [BATCH*NN*CH];
__device__ int    g_done[BATCH];       // stage0 completions per batch (target 72)

__device__ __forceinline__ uint32_t smem_u32(const void* p) {
    uint32_t a;
    asm("{ .reg .u64 t; cvta.to.shared.u64 t, %1; cvt.u32.u64 %0, t; }" : "=r"(a) : "l"(p));
    return a;
}
__device__ __forceinline__ void ldsm4(uint32_t* r, uint32_t addr) {
    asm volatile("ldmatrix.sync.aligned.m8n8.x4.shared.b16 {%0,%1,%2,%3}, [%4];"
        : "=r"(r[0]), "=r"(r[1]), "=r"(r[2]), "=r"(r[3]) : "r"(addr));
}
__device__ __forceinline__ void mma16816(float* c, const uint32_t* a, const uint32_t* b) {
    asm volatile("mma.sync.aligned.m16n8k16.row.col.f32.f16.f16.f32 "
        "{%0,%1,%2,%3}, {%4,%5,%6,%7}, {%8,%9}, {%0,%1,%2,%3};"
        : "+f"(c[0]), "+f"(c[1]), "+f"(c[2]), "+f"(c[3])
        : "r"(a[0]), "r"(a[1]), "r"(a[2]), "r"(a[3]), "r"(b[0]), "r"(b[1]));
}
__device__ __forceinline__ float ex2f(float x) {
    float y; asm("ex2.approx.f32 %0, %1;" : "=f"(y) : "f"(x)); return y;
}
#define CP16(dst, src) asm volatile("cp.async.cg.shared.global [%0], [%1], 16;" :: "r"(dst), "l"(src))
#define CP_COMMIT()    asm volatile("cp.async.commit_group;" ::: "memory")
#define CP_WAIT0()     asm volatile("cp.async.wait_group 0;" ::: "memory")
#define GBAR(id)       asm volatile("bar.sync %0, 128;" :: "r"(id) : "memory")

#define RS 136

// Flash smem: 64-query A tile + per-group double-buffered 64-key B half-tiles
// + QUAD-buffered V (epilogue of tile t-1 overlaps prefetch of tile t+1).
#define FSM_A    0                     // 17408
#define FSM_B    17408                 // 4 x 17408 (group g, buf c at g*2+c)
#define FSM_V    87040                 // 2 groups x 4 bufs x 512 = 4096
#define FSM_RED  91136                 // 192 floats
#define FSM_TOT  92160

// Proj smem map (fits inside FSM_TOT)
#define PSM_F   0
#define PSM_W   34816
#define PSM_QB  69632
#define PSM_KB  70144

// 64-row half-tile prefetch by one 128-thread group (tl = t & 127)
__device__ __forceinline__ void prefetch_half(uint32_t dstBase, const __half* src, int tl) {
    #pragma unroll
    for (int it = 0; it < 8; it++) {
        int idx = it * 128 + tl;
        int r = idx >> 4, g = idx & 15;
        CP16(dstBase + (uint32_t)((r * RS + g * 8) * 2), src + (size_t)r * CH + g * 8);
    }
}

// One 16q x 64k score tile: a-ldsm + 4 b-ldsm + 8 HMMA per k-step.
__device__ __forceinline__ void mma_tile(float (&c)[8][4], uint32_t aBase, uint32_t bB) {
    #pragma unroll
    for (int j = 0; j < 8; j++)
        #pragma unroll
        for (int q = 0; q < 4; q++) c[j][q] = 0.f;
    #pragma unroll
    for (int k = 0; k < 8; k++) {
        uint32_t a[4];
        ldsm4(a, aBase + k * 32);
        #pragma unroll
        for (int j2 = 0; j2 < 4; j2++) {
            uint32_t bb[4];
            ldsm4(bb, bB + j2 * (16 * RS * 2) + k * 32);
            mma16816(c[2 * j2],     a, bb);
            mma16816(c[2 * j2 + 1], a, bb + 2);
        }
    }
}

// Softmax epilogue for one finished tile (independent of concurrent MMA regs).
template<int MODE>
__device__ __forceinline__ void epi_tile(
    const float (&c)[8][4], int tile, int wc, int tid4, const float* sV,
    float L[2], float AX[2], float AY[2])
{
    float Lt0 = 0.f, Lt1 = 0.f;
    #pragma unroll
    for (int j = 0; j < 8; j++) {
        float p0 = ex2f(c[j][0]);
        float p1 = ex2f(c[j][1]);
        float p2 = ex2f(c[j][2]);
        float p3 = ex2f(c[j][3]);
        if (MODE == 0) {
            float vx0 = (float)(j * 8 + tid4 * 2);   // m & 63
            float vx1 = vx0 + 1.f;
            Lt0 += p0 + p1;  Lt1 += p2 + p3;
            AX[0] += p0 * vx0 + p1 * vx1;
            AX[1] += p2 * vx0 + p3 * vx1;
        } else {
            int cl = j * 8 + tid4 * 2;               // local within half
            float2 x2 = *(const float2*)&sV[cl];
            float2 y2 = *(const float2*)&sV[64 + cl];
            L[0]  += p0 + p1;          L[1]  += p2 + p3;
            AX[0] += p0 * x2.x + p1 * x2.y;
            AX[1] += p2 * x2.x + p3 * x2.y;
            AY[0] += p0 * y2.x + p1 * y2.y;
            AY[1] += p2 * y2.x + p3 * y2.y;
        }
    }
    if (MODE == 0) {
        float vy = (float)(2 * tile + wc);           // m >> 6
        L[0] += Lt0;  L[1] += Lt1;
        AY[0] += vy * Lt0;  AY[1] += vy * Lt1;
    }
}

// ---------------------------------------------------------------------------
// Flash body (skewed pipeline): 64-query tile, 24 key tiles of 128 keys,
// two independent 128-thread key-half pipelines (wc), and WITHIN each warp
// the epilogue of tile t-1 is interleaved with the MMA of tile t (double
// accumulator arrays cA/cB, loop unrolled by 2) so MUFU/FMA work fills
// HMMA/ldsm dependency stalls.
// ---------------------------------------------------------------------------
template<int MODE>
__device__ __forceinline__ void flash_body(
    const __half* __restrict__ A, const __half* __restrict__ Bm,
    const float* __restrict__ vsrc, float* __restrict__ out,
    int b, int n0, char* smem)
{
    const uint32_t sb = smem_u32(smem);
    const int t = threadIdx.x, wid = t >> 5, lane = t & 31;
    const int wc = wid >> 2, wr = wid & 3;   // key-half group / query row-block
    const int tl = t & 127;
    const size_t vbase = (size_t)b * 2 * NN;

    {   // query tile: 64 rows (all 256 threads)
        __half* sA = (__half*)smem;
        const __half* src = A + ((size_t)b * NN + n0) * CH;
        #pragma unroll
        for (int it = 0; it < 4; it++) {
            int idx = it * 256 + t;
            int r = idx >> 4, g = idx & 15;
            *(uint4*)(sA + r * RS + g * 8) = *(const uint4*)(src + (size_t)r * CH + g * 8);
        }
    }

    const __half* Bg = Bm + ((size_t)b * NN + wc * 64) * CH;
    const uint32_t bBuf0 = sb + FSM_B + (uint32_t)(wc * 2) * 17408;
    const uint32_t bBuf1 = bBuf0 + 17408;

    auto prefetch_t = [&](int ti) {
        prefetch_half((ti & 1) ? bBuf1 : bBuf0, Bg + (size_t)ti * 128 * CH, tl);
        if (MODE == 1 && tl < 32) {
            const int mn = ti * 128;
            const float* s = (tl < 16)
                ? (vsrc + vbase + mn + wc * 64 + tl * 4)
                : (vsrc + vbase + NN + mn + wc * 64 + (tl - 16) * 4);
            CP16(sb + FSM_V + (uint32_t)(wc * 4 + (ti & 3)) * 512
                 + ((tl < 16) ? tl * 16 : 256 + (tl - 16) * 16), s);
        }
        CP_COMMIT();
    };
    auto sVp = [&](int ti) -> const float* {
        return (const float*)(smem + FSM_V + (wc * 4 + (ti & 3)) * 512);
    };

    prefetch_t(0);

    const int g8 = (lane >> 3) & 1, g16 = lane >> 4, l7 = lane & 7, tid4 = lane & 3;
    const uint32_t aBase = sb + FSM_A + (uint32_t)(((wr * 16 + l7 + g8 * 8) * RS + g16 * 8) * 2);
    const uint32_t bOff  = (uint32_t)(((l7 + g16 * 8) * RS + g8 * 8) * 2);

    CP_WAIT0();
    __syncthreads();       // tile-0 data + sA ready (block-wide, once)
    prefetch_t(1);

    float cA[8][4], cB[8][4];
    float L[2] = {0.f, 0.f}, AX[2] = {0.f, 0.f}, AY[2] = {0.f, 0.f};

    mma_tile(cA, aBase, bBuf0 + bOff);           // tile 0

    #pragma unroll 1
    for (int tt = 1; tt < 23; tt += 2) {
        // step tt: MMA(tt) overlapped with epilogue(tt-1)
        CP_WAIT0(); GBAR(1 + wc);
        prefetch_t(tt + 1);
        mma_tile(cB, aBase, ((tt & 1) ? bBuf1 : bBuf0) + bOff);
        epi_tile<MODE>(cA, tt - 1, wc, tid4, sVp(tt - 1), L, AX, AY);

        // step tt+1: MMA(tt+1) overlapped with epilogue(tt)
        CP_WAIT0(); GBAR(1 + wc);
        if (tt + 2 < 24) prefetch_t(tt + 2);
        mma_tile(cA, aBase, (((tt + 1) & 1) ? bBuf1 : bBuf0) + bOff);
        epi_tile<MODE>(cB, tt, wc, tid4, sVp(tt), L, AX, AY);
    }
    // tail: tile 23 (prefetched at tt=21)
    CP_WAIT0(); GBAR(1 + wc);
    mma_tile(cB, aBase, bBuf1 + bOff);
    epi_tile<MODE>(cA, 22, wc, tid4, sVp(22), L, AX, AY);
    epi_tile<MODE>(cB, 23, wc, tid4, sVp(23), L, AX, AY);

    #pragma unroll
    for (int o = 1; o <= 2; o <<= 1)
        #pragma unroll
        for (int h = 0; h < 2; h++) {
            L[h]  += __shfl_xor_sync(0xffffffffu, L[h],  o);
            AX[h] += __shfl_xor_sync(0xffffffffu, AX[h], o);
            AY[h] += __shfl_xor_sync(0xffffffffu, AY[h], o);
        }

    // Cross-group reduction (block-wide: both groups have left the loop)
    float* red = (float*)(smem + FSM_RED);
    __syncthreads();
    if (wc == 1 && tid4 == 0) {
        #pragma unroll
        for (int h = 0; h < 2; h++) {
            int rl = wr * 16 + h * 8 + (lane >> 2);
            red[rl]       = L[h];
            red[64 + rl]  = AX[h];
            red[128 + rl] = AY[h];
        }
    }
    __syncthreads();
    if (wc == 0 && tid4 == 0) {
        float* ob = out + vbase;
        #pragma unroll
        for (int h = 0; h < 2; h++) {
            int rl = wr * 16 + h * 8 + (lane >> 2);
            float Lt  = L[h]  + red[rl];
            float AXt = AX[h] + red[64 + rl];
            float AYt = AY[h] + red[128 + rl];
            int n = n0 + rl;
            float fx = AXt / Lt, fy = AYt / Lt;
            if (MODE == 0) { fx -= (float)(n & (WW - 1)); fy -= (float)(n >> 6); }
            ob[n] = fx;  ob[NN + n] = fy;
        }
    }
}

// ---------------------------------------------------------------------------
// Proj body (unchanged R8): 128-row tile; q kept in regs as GEMM2 A-fragments.
// ---------------------------------------------------------------------------
__device__ __forceinline__ void proj_body(
    const __half* __restrict__ F0, const float* __restrict__ qw,
    const float* __restrict__ qb,  const float* __restrict__ kw,
    const float* __restrict__ kb,
    __half* __restrict__ QH, __half* __restrict__ KH,
    int b, int n0, char* smem)
{
    __half* sF = (__half*)(smem + PSM_F);
    __half* sW = (__half*)(smem + PSM_W);
    float* qbS = (float*)(smem + PSM_QB);
    float* kbS = (float*)(smem + PSM_KB);
    const uint32_t sbF = smem_u32(sF), sbW = smem_u32(sW);

    const int t = threadIdx.x, wid = t >> 5, lane = t & 31;

    {
        const __half* src = F0 + ((size_t)b * NN + n0) * CH;
        #pragma unroll
        for (int it = 0; it < 8; it++) {
            int idx = it * 256 + t;
            int r = idx >> 4, g = idx & 15;
            *(uint4*)(sF + r * RS + g * 8) = *(const uint4*)(src + (size_t)r * CH + g * 8);
        }
    }
    #pragma unroll
    for (int it = 0; it < 16; it++) {
        int idx = it * 256 + t;
        int r = idx >> 5, g = idx & 31;
        float4 w = *(const float4*)(qw + (size_t)r * CH + g * 4);
        __half h[4] = {__float2half(w.x), __float2half(w.y), __float2half(w.z), __float2half(w.w)};
        *(uint2*)(sW + r * RS + g * 4) = *(uint2*)h;
    }
    if (t < 128) { qbS[t] = qb[t]; kbS[t] = kb[t]; }
    __syncthreads();

    const int g8 = (lane >> 3) & 1, g16 = lane >> 4, l7 = lane & 7, tid4 = lane & 3;
    const uint32_t aBase = sbF + (uint32_t)(((wid * 16 + l7 + g8 * 8) * RS + g16 * 8) * 2);
    const uint32_t bBase = sbW + (uint32_t)(((l7 + g16 * 8) * RS + g8 * 8) * 2);

    float c[16][4];
    #pragma unroll
    for (int j = 0; j < 16; j++)
        #pragma unroll
        for (int q = 0; q < 4; q++) c[j][q] = 0.f;
    #pragma unroll
    for (int k = 0; k < 8; k++) {
        uint32_t a[4];
        ldsm4(a, aBase + k * 32);
        #pragma unroll
        for (int j2 = 0; j2 < 8; j2++) {
            uint32_t bb[4];
            ldsm4(bb, bBase + j2 * (16 * RS * 2) + k * 32);
            mma16816(c[2 * j2],     a, bb);
            mma16816(c[2 * j2 + 1], a, bb + 2);
        }
    }

    uint32_t hq[16][2];
    const int r0 = wid * 16 + (lane >> 2);
    #pragma unroll
    for (int j = 0; j < 16; j++) {
        int col = j * 8 + tid4 * 2;
        float b0 = qbS[col], b1 = qbS[col + 1];
        __half2 v0 = __floats2half2_rn(c[j][0] + b0, c[j][1] + b1);
        __half2 v1 = __floats2half2_rn(c[j][2] + b0, c[j][3] + b1);
        hq[j][0] = *(uint32_t*)&v0;
        hq[j][1] = *(uint32_t*)&v1;
        *(uint32_t*)(QH + ((size_t)b * NN + n0 + r0) * CH + col)     = hq[j][0];
        *(uint32_t*)(QH + ((size_t)b * NN + n0 + r0 + 8) * CH + col) = hq[j][1];
    }

    __syncthreads();
    #pragma unroll
    for (int it = 0; it < 16; it++) {
        int idx = it * 256 + t;
        int r = idx >> 5, g = idx & 31;
        float4 w = *(const float4*)(kw + (size_t)r * CH + g * 4);
        __half h[4] = {__float2half(w.x), __float2half(w.y), __float2half(w.z), __float2half(w.w)};
        *(uint2*)(sW + r * RS + g * 4) = *(uint2*)h;
    }
    __syncthreads();

    float c2[16][4];
    #pragma unroll
    for (int j = 0; j < 16; j++)
        #pragma unroll
        for (int q = 0; q < 4; q++) c2[j][q] = 0.f;
    #pragma unroll
    for (int kk = 0; kk < 8; kk++) {
        uint32_t a[4] = { hq[2 * kk][0], hq[2 * kk][1], hq[2 * kk + 1][0], hq[2 * kk + 1][1] };
        #pragma unroll
        for (int j2 = 0; j2 < 8; j2++) {
            uint32_t bb[4];
            ldsm4(bb, bBase + j2 * (16 * RS * 2) + kk * 32);
            mma16816(c2[2 * j2],     a, bb);
            mma16816(c2[2 * j2 + 1], a, bb + 2);
        }
    }
    #pragma unroll
    for (int j = 0; j < 16; j++) {
        int col = j * 8 + tid4 * 2;
        float b0 = kbS[col], b1 = kbS[col + 1];
        __half2 v0 = __floats2half2_rn((c2[j][0] + b0) * S2F, (c2[j][1] + b1) * S2F);
        __half2 v1 = __floats2half2_rn((c2[j][2] + b0) * S2F, (c2[j][3] + b1) * S2F);
        *(uint32_t*)(KH + ((size_t)b * NN + n0 + r0) * CH + col)     = *(uint32_t*)&v0;
        *(uint32_t*)(KH + ((size_t)b * NN + n0 + r0 + 8) * CH + col) = *(uint32_t*)&v1;
    }
}

// ---------------------------------------------------------------------------
// Fused pipeline kernel (R10 grid): 960 CTAs in bid order:
//   bid   0..191 : proj   (b = idx/24, n0 = (idx%24)*128)  -> g_done[b] += 1
//   bid 192..575 : flash0 (b = idx/48, n0 = (idx%48)*64)   -> g_done[b] += 1
//   bid 576..959 : flash1 — spins until g_done[b] == 72.
// g_done[] zeroed by the conv kernel preceding this launch.
// ---------------------------------------------------------------------------
__global__ void __launch_bounds__(256, 2) fused_kernel(
    const __half* __restrict__ f0h, const __half* __restrict__ f1h,
    const float* __restrict__ qw, const float* __restrict__ qb,
    const float* __restrict__ kw, const float* __restrict__ kb,
    __half* __restrict__ qh, __half* __restrict__ kh,
    float* __restrict__ flow_pred, float* __restrict__ flow)
{
    extern __shared__ char smem[];
    const int bid = blockIdx.x;

    if (bid < 192) {
        const int idx = bid, b = idx / 24;
        proj_body(f0h, qw, qb, kw, kb, qh, kh, b, (idx % 24) * 128, smem);
        __threadfence();
        __syncthreads();
        if (threadIdx.x == 0) atomicAdd(&g_done[b], 1);
    } else if (bid < 576) {
        const int idx = bid - 192, b = idx / 48;
        flash_body<0>(f0h, f1h, nullptr, flow_pred, b, (idx % 48) * 64, smem);
        __threadfence();
        __syncthreads();
        if (threadIdx.x == 0) atomicAdd(&g_done[b], 1);
    } else {
        const int idx = bid - 576, b = idx / 48;
        if (threadIdx.x == 0) {
            while (atomicAdd(&g_done[b], 0) < 72) __nanosleep(200);
            __threadfence();
        }
        __syncthreads();
        flash_body<1>(qh, kh, flow_pred, flow, b, (idx % 48) * 64, smem);
    }
}

// ---------------------------------------------------------------------------
// Fused transpose+convert (re-zeroes g_done): z<8 f0->f0h (x1), z>=8 f1 (xS2)
// ---------------------------------------------------------------------------
__global__ void __launch_bounds__(256) convH2_kernel(
    const float* __restrict__ f0, const float* __restrict__ f1,
    __half* __restrict__ o0, __half* __restrict__ o1)
{
    __shared__ float tile[32][33];
    if (blockIdx.x == 0 && blockIdx.y == 0 && blockIdx.z == 0 &&
        threadIdx.x < BATCH && threadIdx.y == 0)
        g_done[threadIdx.x] = 0;

    const int z = blockIdx.z, b = z & 7;
    const float* in = (z < 8) ? f0 : f1;
    __half* out = (z < 8) ? o0 : o1;
    const float scale = (z < 8) ? 1.0f : S2F;
    const int n0 = blockIdx.x * 32, c0 = blockIdx.y * 32;
    const int tx = threadIdx.x, ty = threadIdx.y;

    const float* ip = in + ((size_t)b * CH + c0) * NN + n0;
    #pragma unroll
    for (int i = 0; i < 4; i++) {
        int c = ty + i * 8;
        tile[c][tx] = ip[(size_t)c * NN + tx];
    }
    __syncthreads();
    __half* op = out + ((size_t)b * NN + n0) * CH + c0;
    #pragma unroll
    for (int i = 0; i < 4; i++) {
        int nr = ty + i * 8;
        op[(size_t)nr * CH + tx] = __float2half(tile[tx][nr] * scale);
    }
}

extern "C" void kernel_launch(void* const* d_in, const int* in_sizes, int n_in,
                              void* d_out, int out_size)
{
    const float* f0 = (const float*)d_in[0];
    const float* f1 = (const float*)d_in[1];
    const float* qw = (const float*)d_in[2];
    const float* qb = (const float*)d_in[3];
    const float* kw = (const float*)d_in[4];
    const float* kb = (const float*)d_in[5];

    float* out       = (float*)d_out;
    float* flow      = out;
    float* flow_pred = out + (size_t)BATCH * 2 * NN;

    void* p;
    cudaGetSymbolAddress(&p, g_f0h); __half* f0h = (__half*)p;
    cudaGetSymbolAddress(&p, g_f1h); __half* f1h = (__half*)p;
    cudaGetSymbolAddress(&p, g_qh);  __half* qh  = (__half*)p;
    cudaGetSymbolAddress(&p, g_kh);  __half* kh  = (__half*)p;

    cudaFuncSetAttribute(fused_kernel, cudaFuncAttributeMaxDynamicSharedMemorySize, FSM_TOT);

    dim3 cgrid(NN / 32, CH / 32, 2 * BATCH);
    dim3 cblk(32, 8);

    convH2_kernel<<<cgrid, cblk>>>(f0, f1, f0h, f1h);
    fused_kernel<<<960, 256, FSM_TOT>>>(f0h, f1h, qw, qb, kw, kb, qh, kh,
                                        flow_pred, flow);
}

// round 13
// speedup vs baseline: 1.0880x; 1.0362x over previous
#include <cuda_runtime.h>
#include <cuda_fp16.h>
#include <cstdint>

#define BATCH 8
#define CH    128
#define HH    48
#define WW    64
#define NN    (HH*WW)   // 3072

#define S2F ((float)(1.4426950408889634 * 0.088388347648318447))

__device__ __half g_f0h[BATCH*NN*CH];
__device__ __half g_f1h[BATCH*NN*CH];
__device__ __half g_qh [BATCH*NN*CH];
__device__ __half g_kh [BATCH*NN*CH];
__device__ int    g_done[BATCH];       // stage0 completions per batch (target 72)

__device__ __forceinline__ uint32_t smem_u32(const void* p) {
    uint32_t a;
    asm("{ .reg .u64 t; cvta.to.shared.u64 t, %1; cvt.u32.u64 %0, t; }" : "=r"(a) : "l"(p));
    return a;
}
__device__ __forceinline__ void ldsm4(uint32_t* r, uint32_t addr) {
    asm volatile("ldmatrix.sync.aligned.m8n8.x4.shared.b16 {%0,%1,%2,%3}, [%4];"
        : "=r"(r[0]), "=r"(r[1]), "=r"(r[2]), "=r"(r[3]) : "r"(addr));
}
__device__ __forceinline__ void mma16816(float* c, const uint32_t* a, const uint32_t* b) {
    asm volatile("mma.sync.aligned.m16n8k16.row.col.f32.f16.f16.f32 "
        "{%0,%1,%2,%3}, {%4,%5,%6,%7}, {%8,%9}, {%0,%1,%2,%3};"
        : "+f"(c[0]), "+f"(c[1]), "+f"(c[2]), "+f"(c[3])
        : "r"(a[0]), "r"(a[1]), "r"(a[2]), "r"(a[3]), "r"(b[0]), "r"(b[1]));
}
__device__ __forceinline__ float ex2f(float x) {
    float y; asm("ex2.approx.f32 %0, %1;" : "=f"(y) : "f"(x)); return y;
}
#define CP16(dst, src) asm volatile("cp.async.cg.shared.global [%0], [%1], 16;" :: "r"(dst), "l"(src))
#define CP_COMMIT()    asm volatile("cp.async.commit_group;" ::: "memory")
#define CP_WAIT0()     asm volatile("cp.async.wait_group 0;" ::: "memory")
#define GBAR(id)       asm volatile("bar.sync %0, 128;" :: "r"(id) : "memory")

#define RS 136

// Flash smem: 64-query A tile + per-group double-buffered 64-key B half-tiles
#define FSM_A    0          // 17408
#define FSM_B    17408      // 4 x 17408 (group g, buf c at g*2+c) -> ends 87040
#define FSM_V    87040      // 4 x 512
#define FSM_RED  89088      // 576 floats (3 partial sets x 192)
#define FSM_TOT  91648

// Proj smem map (fits inside FSM_TOT)
#define PSM_F   0
#define PSM_W   34816
#define PSM_QB  69632
#define PSM_KB  70144

// 64-row half-tile prefetch by one 128-thread group (tl = t & 127)
__device__ __forceinline__ void prefetch_half(uint32_t dstBase, const __half* src, int tl) {
    #pragma unroll
    for (int it = 0; it < 8; it++) {
        int idx = it * 128 + tl;
        int r = idx >> 4, g = idx & 15;
        CP16(dstBase + (uint32_t)((r * RS + g * 8) * 2), src + (size_t)r * CH + g * 8);
    }
}

// ---------------------------------------------------------------------------
// Flash body: 64-query tile, 24 key tiles of 128 keys.
// Two independent 128-thread key-half pipelines (wc) as in R10, but warp
// tiles are now SQUARE 32q x 32k: group warps = 2 q-blocks (wq) x 2 key-
// quarters (wk). Per-tile LDSM traffic drops 160 KB -> 128 KB and the
// ldsm:HMMA ratio improves 40:64 -> 32:64. Final softmax reduction merges
// 4 partials per row (wc x wk) through smem.
// ---------------------------------------------------------------------------
template<int MODE>
__device__ __forceinline__ void flash_body(
    const __half* __restrict__ A, const __half* __restrict__ Bm,
    const float* __restrict__ vsrc, float* __restrict__ out,
    int b, int n0, char* smem)
{
    const uint32_t sb = smem_u32(smem);
    const int t = threadIdx.x, wid = t >> 5, lane = t & 31;
    const int wc = wid >> 2;             // key-half group
    const int wq = (wid >> 1) & 1;       // query block (32 rows)
    const int wk = wid & 1;              // key quarter (32 keys) within half
    const int tl = t & 127;
    const size_t vbase = (size_t)b * 2 * NN;

    {   // query tile: 64 rows (all 256 threads)
        __half* sA = (__half*)smem;
        const __half* src = A + ((size_t)b * NN + n0) * CH;
        #pragma unroll
        for (int it = 0; it < 4; it++) {
            int idx = it * 256 + t;
            int r = idx >> 4, g = idx & 15;
            *(uint4*)(sA + r * RS + g * 8) = *(const uint4*)(src + (size_t)r * CH + g * 8);
        }
    }

    // Group wc's source rows for tile T start at T*128 + wc*64
    const __half* Bg = Bm + ((size_t)b * NN + wc * 64) * CH;
    const uint32_t bBuf0 = sb + FSM_B + (uint32_t)(wc * 2) * 17408;
    const uint32_t bBuf1 = bBuf0 + 17408;
    const uint32_t vBuf0 = sb + FSM_V + (uint32_t)(wc * 2) * 512;
    const uint32_t vBuf1 = vBuf0 + 512;

    prefetch_half(bBuf0, Bg, tl);
    if (MODE == 1 && tl < 32) {
        const float* s = (tl < 16) ? (vsrc + vbase + wc * 64 + tl * 4)
                                   : (vsrc + vbase + NN + wc * 64 + (tl - 16) * 4);
        CP16(vBuf0 + ((tl < 16) ? tl * 16 : 256 + (tl - 16) * 16), s);
    }
    CP_COMMIT();

    const int g8 = (lane >> 3) & 1, g16 = lane >> 4, l7 = lane & 7, tid4 = lane & 3;
    // A: rows wq*32 .. +31 (two 16-row ldsm blocks)
    const uint32_t aB0 = sb + FSM_A + (uint32_t)(((wq * 32 + l7 + g8 * 8) * RS + g16 * 8) * 2);
    const uint32_t aB1 = aB0 + (uint32_t)(16 * RS * 2);
    // B: this warp's 32-key quarter within the half buffer
    const uint32_t bOff = (uint32_t)(((wk * 32 + l7 + g16 * 8) * RS + g8 * 8) * 2);

    // Tile-0 halves + sA ready (block-wide once)
    CP_WAIT0();
    __syncthreads();

    // Prefetch tile 1 into buf1 (per group)
    prefetch_half(bBuf1, Bg + (size_t)128 * CH, tl);
    if (MODE == 1 && tl < 32) {
        const float* s = (tl < 16) ? (vsrc + vbase + 128 + wc * 64 + tl * 4)
                                   : (vsrc + vbase + NN + 128 + wc * 64 + (tl - 16) * 4);
        CP16(vBuf1 + ((tl < 16) ? tl * 16 : 256 + (tl - 16) * 16), s);
    }
    CP_COMMIT();

    float L[2][2], AX[2][2], AY[2][2];
    #pragma unroll
    for (int rb = 0; rb < 2; rb++)
        #pragma unroll
        for (int h = 0; h < 2; h++) { L[rb][h] = 0.f; AX[rb][h] = 0.f; AY[rb][h] = 0.f; }

    for (int tile = 0; tile < NN / 128; tile++) {
        const uint32_t cur = tile & 1;
        if (tile > 0) {
            CP_WAIT0();                    // this tile's half ready
            GBAR(1 + wc);                  // group done reading buf being refilled
            if (tile + 1 < NN / 128) {
                const int mn = (tile + 1) * 128;
                prefetch_half(cur ? bBuf0 : bBuf1, Bg + (size_t)mn * CH, tl);
                if (MODE == 1 && tl < 32) {
                    const float* s = (tl < 16)
                        ? (vsrc + vbase + mn + wc * 64 + tl * 4)
                        : (vsrc + vbase + NN + mn + wc * 64 + (tl - 16) * 4);
                    CP16((cur ? vBuf0 : vBuf1)
                         + ((tl < 16) ? tl * 16 : 256 + (tl - 16) * 16), s);
                }
                CP_COMMIT();
            }
        }

        const uint32_t bB = (cur ? bBuf1 : bBuf0) + bOff;
        const float* sV = (const float*)(smem + ((cur ? vBuf1 : vBuf0) - sb));

        // c[rb][j][q]: rb = 16-row block, j = n8 column block (4 x 8 = 32 keys)
        float c[2][4][4];
        #pragma unroll
        for (int rb = 0; rb < 2; rb++)
            #pragma unroll
            for (int j = 0; j < 4; j++)
                #pragma unroll
                for (int q = 0; q < 4; q++) c[rb][j][q] = 0.f;

        #pragma unroll
        for (int k = 0; k < 8; k++) {
            uint32_t a0[4], a1[4];
            ldsm4(a0, aB0 + k * 32);
            ldsm4(a1, aB1 + k * 32);
            #pragma unroll
            for (int j2 = 0; j2 < 2; j2++) {
                uint32_t bb[4];
                ldsm4(bb, bB + j2 * (16 * RS * 2) + k * 32);
                mma16816(c[0][j2 * 2],     a0, bb);
                mma16816(c[0][j2 * 2 + 1], a0, bb + 2);
                mma16816(c[1][j2 * 2],     a1, bb);
                mma16816(c[1][j2 * 2 + 1], a1, bb + 2);
            }
        }

        #pragma unroll
        for (int rb = 0; rb < 2; rb++) {
            float Lt0 = 0.f, Lt1 = 0.f;
            #pragma unroll
            for (int j = 0; j < 4; j++) {
                float p0 = ex2f(c[rb][j][0]);
                float p1 = ex2f(c[rb][j][1]);
                float p2 = ex2f(c[rb][j][2]);
                float p3 = ex2f(c[rb][j][3]);
                if (MODE == 0) {
                    float vx0 = (float)(wk * 32 + j * 8 + tid4 * 2);  // m & 63
                    float vx1 = vx0 + 1.f;
                    Lt0 += p0 + p1;  Lt1 += p2 + p3;
                    AX[rb][0] += p0 * vx0 + p1 * vx1;
                    AX[rb][1] += p2 * vx0 + p3 * vx1;
                } else {
                    int cl = wk * 32 + j * 8 + tid4 * 2;              // within half
                    float2 x2 = *(const float2*)&sV[cl];
                    float2 y2 = *(const float2*)&sV[64 + cl];
                    L[rb][0]  += p0 + p1;          L[rb][1]  += p2 + p3;
                    AX[rb][0] += p0 * x2.x + p1 * x2.y;
                    AX[rb][1] += p2 * x2.x + p3 * x2.y;
                    AY[rb][0] += p0 * y2.x + p1 * y2.y;
                    AY[rb][1] += p2 * y2.x + p3 * y2.y;
                }
            }
            if (MODE == 0) {
                float vy = (float)(2 * tile + wc);                    // m >> 6
                L[rb][0] += Lt0;  L[rb][1] += Lt1;
                AY[rb][0] += vy * Lt0;  AY[rb][1] += vy * Lt1;
            }
        }
    }

    #pragma unroll
    for (int o = 1; o <= 2; o <<= 1)
        #pragma unroll
        for (int rb = 0; rb < 2; rb++)
            #pragma unroll
            for (int h = 0; h < 2; h++) {
                L[rb][h]  += __shfl_xor_sync(0xffffffffu, L[rb][h],  o);
                AX[rb][h] += __shfl_xor_sync(0xffffffffu, AX[rb][h], o);
                AY[rb][h] += __shfl_xor_sync(0xffffffffu, AY[rb][h], o);
            }

    // Cross-warp reduction: each row has 4 partials (wc x wk). Warps with
    // slot != 0 publish; (wc,wk)=(0,0) warps (both wq) combine and write.
    float* red = (float*)(smem + FSM_RED);
    const int slot = wc * 2 + wk;   // 0..3
    __syncthreads();                // all groups out of the mainloop
    if (slot != 0 && tid4 == 0) {
        #pragma unroll
        for (int rb = 0; rb < 2; rb++)
            #pragma unroll
            for (int h = 0; h < 2; h++) {
                int rl = wq * 32 + rb * 16 + h * 8 + (lane >> 2);
                float* rs = red + (slot - 1) * 192;
                rs[rl]       = L[rb][h];
                rs[64 + rl]  = AX[rb][h];
                rs[128 + rl] = AY[rb][h];
            }
    }
    __syncthreads();
    if (slot == 0 && tid4 == 0) {
        float* ob = out + vbase;
        #pragma unroll
        for (int rb = 0; rb < 2; rb++)
            #pragma unroll
            for (int h = 0; h < 2; h++) {
                int rl = wq * 32 + rb * 16 + h * 8 + (lane >> 2);
                float Lt  = L[rb][h]  + red[rl]       + red[192 + rl]       + red[384 + rl];
                float AXt = AX[rb][h] + red[64 + rl]  + red[192 + 64 + rl]  + red[384 + 64 + rl];
                float AYt = AY[rb][h] + red[128 + rl] + red[192 + 128 + rl] + red[384 + 128 + rl];
                int n = n0 + rl;
                float fx = AXt / Lt, fy = AYt / Lt;
                if (MODE == 0) { fx -= (float)(n & (WW - 1)); fy -= (float)(n >> 6); }
                ob[n] = fx;  ob[NN + n] = fy;
            }
    }
}

// ---------------------------------------------------------------------------
// Proj body (unchanged R8): 128-row tile; q kept in regs as GEMM2 A-fragments.
// ---------------------------------------------------------------------------
__device__ __forceinline__ void proj_body(
    const __half* __restrict__ F0, const float* __restrict__ qw,
    const float* __restrict__ qb,  const float* __restrict__ kw,
    const float* __restrict__ kb,
    __half* __restrict__ QH, __half* __restrict__ KH,
    int b, int n0, char* smem)
{
    __half* sF = (__half*)(smem + PSM_F);
    __half* sW = (__half*)(smem + PSM_W);
    float* qbS = (float*)(smem + PSM_QB);
    float* kbS = (float*)(smem + PSM_KB);
    const uint32_t sbF = smem_u32(sF), sbW = smem_u32(sW);

    const int t = threadIdx.x, wid = t >> 5, lane = t & 31;

    {
        const __half* src = F0 + ((size_t)b * NN + n0) * CH;
        #pragma unroll
        for (int it = 0; it < 8; it++) {
            int idx = it * 256 + t;
            int r = idx >> 4, g = idx & 15;
            *(uint4*)(sF + r * RS + g * 8) = *(const uint4*)(src + (size_t)r * CH + g * 8);
        }
    }
    #pragma unroll
    for (int it = 0; it < 16; it++) {
        int idx = it * 256 + t;
        int r = idx >> 5, g = idx & 31;
        float4 w = *(const float4*)(qw + (size_t)r * CH + g * 4);
        __half h[4] = {__float2half(w.x), __float2half(w.y), __float2half(w.z), __float2half(w.w)};
        *(uint2*)(sW + r * RS + g * 4) = *(uint2*)h;
    }
    if (t < 128) { qbS[t] = qb[t]; kbS[t] = kb[t]; }
    __syncthreads();

    const int g8 = (lane >> 3) & 1, g16 = lane >> 4, l7 = lane & 7, tid4 = lane & 3;
    const uint32_t aBase = sbF + (uint32_t)(((wid * 16 + l7 + g8 * 8) * RS + g16 * 8) * 2);
    const uint32_t bBase = sbW + (uint32_t)(((l7 + g16 * 8) * RS + g8 * 8) * 2);

    float c[16][4];
    #pragma unroll
    for (int j = 0; j < 16; j++)
        #pragma unroll
        for (int q = 0; q < 4; q++) c[j][q] = 0.f;
    #pragma unroll
    for (int k = 0; k < 8; k++) {
        uint32_t a[4];
        ldsm4(a, aBase + k * 32);
        #pragma unroll
        for (int j2 = 0; j2 < 8; j2++) {
            uint32_t bb[4];
            ldsm4(bb, bBase + j2 * (16 * RS * 2) + k * 32);
            mma16816(c[2 * j2],     a, bb);
            mma16816(c[2 * j2 + 1], a, bb + 2);
        }
    }

    uint32_t hq[16][2];
    const int r0 = wid * 16 + (lane >> 2);
    #pragma unroll
    for (int j = 0; j < 16; j++) {
        int col = j * 8 + tid4 * 2;
        float b0 = qbS[col], b1 = qbS[col + 1];
        __half2 v0 = __floats2half2_rn(c[j][0] + b0, c[j][1] + b1);
        __half2 v1 = __floats2half2_rn(c[j][2] + b0, c[j][3] + b1);
        hq[j][0] = *(uint32_t*)&v0;
        hq[j][1] = *(uint32_t*)&v1;
        *(uint32_t*)(QH + ((size_t)b * NN + n0 + r0) * CH + col)     = hq[j][0];
        *(uint32_t*)(QH + ((size_t)b * NN + n0 + r0 + 8) * CH + col) = hq[j][1];
    }

    __syncthreads();
    #pragma unroll
    for (int it = 0; it < 16; it++) {
        int idx = it * 256 + t;
        int r = idx >> 5, g = idx & 31;
        float4 w = *(const float4*)(kw + (size_t)r * CH + g * 4);
        __half h[4] = {__float2half(w.x), __float2half(w.y), __float2half(w.z), __float2half(w.w)};
        *(uint2*)(sW + r * RS + g * 4) = *(uint2*)h;
    }
    __syncthreads();

    float c2[16][4];
    #pragma unroll
    for (int j = 0; j < 16; j++)
        #pragma unroll
        for (int q = 0; q < 4; q++) c2[j][q] = 0.f;
    #pragma unroll
    for (int kk = 0; kk < 8; kk++) {
        uint32_t a[4] = { hq[2 * kk][0], hq[2 * kk][1], hq[2 * kk + 1][0], hq[2 * kk + 1][1] };
        #pragma unroll
        for (int j2 = 0; j2 < 8; j2++) {
            uint32_t bb[4];
            ldsm4(bb, bBase + j2 * (16 * RS * 2) + kk * 32);
            mma16816(c2[2 * j2],     a, bb);
            mma16816(c2[2 * j2 + 1], a, bb + 2);
        }
    }
    #pragma unroll
    for (int j = 0; j < 16; j++) {
        int col = j * 8 + tid4 * 2;
        float b0 = kbS[col], b1 = kbS[col + 1];
        __half2 v0 = __floats2half2_rn((c2[j][0] + b0) * S2F, (c2[j][1] + b1) * S2F);
        __half2 v1 = __floats2half2_rn((c2[j][2] + b0) * S2F, (c2[j][3] + b1) * S2F);
        *(uint32_t*)(KH + ((size_t)b * NN + n0 + r0) * CH + col)     = *(uint32_t*)&v0;
        *(uint32_t*)(KH + ((size_t)b * NN + n0 + r0 + 8) * CH + col) = *(uint32_t*)&v1;
    }
}

// ---------------------------------------------------------------------------
// Fused pipeline kernel (R10 grid): 960 CTAs in bid order:
//   bid   0..191 : proj   (b = idx/24, n0 = (idx%24)*128)  -> g_done[b] += 1
//   bid 192..575 : flash0 (b = idx/48, n0 = (idx%48)*64)   -> g_done[b] += 1
//   bid 576..959 : flash1 — spins until g_done[b] == 72.
// g_done[] zeroed by the conv kernel preceding this launch.
// ---------------------------------------------------------------------------
__global__ void __launch_bounds__(256, 2) fused_kernel(
    const __half* __restrict__ f0h, const __half* __restrict__ f1h,
    const float* __restrict__ qw, const float* __restrict__ qb,
    const float* __restrict__ kw, const float* __restrict__ kb,
    __half* __restrict__ qh, __half* __restrict__ kh,
    float* __restrict__ flow_pred, float* __restrict__ flow)
{
    extern __shared__ char smem[];
    const int bid = blockIdx.x;

    if (bid < 192) {
        const int idx = bid, b = idx / 24;
        proj_body(f0h, qw, qb, kw, kb, qh, kh, b, (idx % 24) * 128, smem);
        __threadfence();
        __syncthreads();
        if (threadIdx.x == 0) atomicAdd(&g_done[b], 1);
    } else if (bid < 576) {
        const int idx = bid - 192, b = idx / 48;
        flash_body<0>(f0h, f1h, nullptr, flow_pred, b, (idx % 48) * 64, smem);
        __threadfence();
        __syncthreads();
        if (threadIdx.x == 0) atomicAdd(&g_done[b], 1);
    } else {
        const int idx = bid - 576, b = idx / 48;
        if (threadIdx.x == 0) {
            while (atomicAdd(&g_done[b], 0) < 72) __nanosleep(200);
            __threadfence();
        }
        __syncthreads();
        flash_body<1>(qh, kh, flow_pred, flow, b, (idx % 48) * 64, smem);
    }
}

// ---------------------------------------------------------------------------
// Fused transpose+convert (re-zeroes g_done): z<8 f0->f0h (x1), z>=8 f1 (xS2)
// ---------------------------------------------------------------------------
__global__ void __launch_bounds__(256) convH2_kernel(
    const float* __restrict__ f0, const float* __restrict__ f1,
    __half* __restrict__ o0, __half* __restrict__ o1)
{
    __shared__ float tile[32][33];
    if (blockIdx.x == 0 && blockIdx.y == 0 && blockIdx.z == 0 &&
        threadIdx.x < BATCH && threadIdx.y == 0)
        g_done[threadIdx.x] = 0;

    const int z = blockIdx.z, b = z & 7;
    const float* in = (z < 8) ? f0 : f1;
    __half* out = (z < 8) ? o0 : o1;
    const float scale = (z < 8) ? 1.0f : S2F;
    const int n0 = blockIdx.x * 32, c0 = blockIdx.y * 32;
    const int tx = threadIdx.x, ty = threadIdx.y;

    const float* ip = in + ((size_t)b * CH + c0) * NN + n0;
    #pragma unroll
    for (int i = 0; i < 4; i++) {
        int c = ty + i * 8;
        tile[c][tx] = ip[(size_t)c * NN + tx];
    }
    __syncthreads();
    __half* op = out + ((size_t)b * NN + n0) * CH + c0;
    #pragma unroll
    for (int i = 0; i < 4; i++) {
        int nr = ty + i * 8;
        op[(size_t)nr * CH + tx] = __float2half(tile[tx][nr] * scale);
    }
}

extern "C" void kernel_launch(void* const* d_in, const int* in_sizes, int n_in,
                              void* d_out, int out_size)
{
    const float* f0 = (const float*)d_in[0];
    const float* f1 = (const float*)d_in[1];
    const float* qw = (const float*)d_in[2];
    const float* qb = (const float*)d_in[3];
    const float* kw = (const float*)d_in[4];
    const float* kb = (const float*)d_in[5];

    float* out       = (float*)d_out;
    float* flow      = out;
    float* flow_pred = out + (size_t)BATCH * 2 * NN;

    void* p;
    cudaGetSymbolAddress(&p, g_f0h); __half* f0h = (__half*)p;
    cudaGetSymbolAddress(&p, g_f1h); __half* f1h = (__half*)p;
    cudaGetSymbolAddress(&p, g_qh);  __half* qh  = (__half*)p;
    cudaGetSymbolAddress(&p, g_kh);  __half* kh  = (__half*)p;

    cudaFuncSetAttribute(fused_kernel, cudaFuncAttributeMaxDynamicSharedMemorySize, FSM_TOT);

    dim3 cgrid(NN / 32, CH / 32, 2 * BATCH);
    dim3 cblk(32, 8);

    convH2_kernel<<<cgrid, cblk>>>(f0, f1, f0h, f1h);
    fused_kernel<<<960, 256, FSM_TOT>>>(f0h, f1h, qw, qb, kw, kb, qh, kh,
                                        flow_pred, flow);
}

// round 15
// speedup vs baseline: 1.1172x; 1.0268x over previous
#include <cuda_runtime.h>
#include <cuda_fp16.h>
#include <cstdint>

#define BATCH 8
#define CH    128
#define HH    48
#define WW    64
#define NN    (HH*WW)   // 3072

#define S2F ((float)(1.4426950408889634 * 0.088388347648318447))

__device__ __half g_f0h[BATCH*NN*CH];
__device__ __half g_f1h[BATCH*NN*CH];
__device__ __half g_qh [BATCH*NN*CH];
__device__ __half g_kh [BATCH*NN*CH];
__device__ int    g_done[BATCH];       // stage0 completions per batch (target 72)

__device__ __forceinline__ uint32_t smem_u32(const void* p) {
    uint32_t a;
    asm("{ .reg .u64 t; cvta.to.shared.u64 t, %1; cvt.u32.u64 %0, t; }" : "=r"(a) : "l"(p));
    return a;
}
__device__ __forceinline__ void ldsm4(uint32_t* r, uint32_t addr) {
    asm volatile("ldmatrix.sync.aligned.m8n8.x4.shared.b16 {%0,%1,%2,%3}, [%4];"
        : "=r"(r[0]), "=r"(r[1]), "=r"(r[2]), "=r"(r[3]) : "r"(addr));
}
__device__ __forceinline__ void mma16816(float* c, const uint32_t* a, const uint32_t* b) {
    asm volatile("mma.sync.aligned.m16n8k16.row.col.f32.f16.f16.f32 "
        "{%0,%1,%2,%3}, {%4,%5,%6,%7}, {%8,%9}, {%0,%1,%2,%3};"
        : "+f"(c[0]), "+f"(c[1]), "+f"(c[2]), "+f"(c[3])
        : "r"(a[0]), "r"(a[1]), "r"(a[2]), "r"(a[3]), "r"(b[0]), "r"(b[1]));
}
__device__ __forceinline__ float ex2f(float x) {
    float y; asm("ex2.approx.f32 %0, %1;" : "=f"(y) : "f"(x)); return y;
}
#define CP16(dst, src) asm volatile("cp.async.cg.shared.global [%0], [%1], 16;" :: "r"(dst), "l"(src))
#define CP_COMMIT()    asm volatile("cp.async.commit_group;" ::: "memory")
#define CP_WAIT0()     asm volatile("cp.async.wait_group 0;" ::: "memory")
#define GBAR(id)       asm volatile("bar.sync %0, 128;" :: "r"(id) : "memory")

#define RS 136

// Flash smem: 64-query A tile + per-group double-buffered 64-key B half-tiles
#define FSM_A    0          // 17408
#define FSM_B    17408      // 4 x 17408 (group g, buf c at g*2+c) -> ends 87040
#define FSM_V    87040      // 4 x 512
#define FSM_RED  89088      // 576 floats (3 partial sets x 192)
#define FSM_TOT  91648

// Proj smem map (fits inside FSM_TOT)
#define PSM_F   0
#define PSM_W   34816
#define PSM_QB  69632
#define PSM_KB  70144

// 64-row half-tile prefetch by one 128-thread group (tl = t & 127)
__device__ __forceinline__ void prefetch_half(uint32_t dstBase, const __half* src, int tl) {
    #pragma unroll
    for (int it = 0; it < 8; it++) {
        int idx = it * 128 + tl;
        int r = idx >> 4, g = idx & 15;
        CP16(dstBase + (uint32_t)((r * RS + g * 8) * 2), src + (size_t)r * CH + g * 8);
    }
}

// ---------------------------------------------------------------------------
// Flash body (R13 square-tile skeleton + a0 hoist; fp32 ex2 restored):
//  - 64-query tile, 24 key tiles of 128 keys; two independent 128-thread
//    key-half pipelines (wc); warp tiles 32q x 32k (wq x wk).
//  - a0 row-block (16 rows) A fragments HOISTED into registers (crossbar -25%).
//  - epilogue exponentials in fp32 (ex2.approx.f32) — precision floor.
// ---------------------------------------------------------------------------
template<int MODE>
__device__ __forceinline__ void flash_body(
    const __half* __restrict__ A, const __half* __restrict__ Bm,
    const float* __restrict__ vsrc, float* __restrict__ out,
    int b, int n0, char* smem)
{
    const uint32_t sb = smem_u32(smem);
    const int t = threadIdx.x, wid = t >> 5, lane = t & 31;
    const int wc = wid >> 2;             // key-half group
    const int wq = (wid >> 1) & 1;       // query block (32 rows)
    const int wk = wid & 1;              // key quarter (32 keys) within half
    const int tl = t & 127;
    const size_t vbase = (size_t)b * 2 * NN;

    {   // query tile: 64 rows (all 256 threads)
        __half* sA = (__half*)smem;
        const __half* src = A + ((size_t)b * NN + n0) * CH;
        #pragma unroll
        for (int it = 0; it < 4; it++) {
            int idx = it * 256 + t;
            int r = idx >> 4, g = idx & 15;
            *(uint4*)(sA + r * RS + g * 8) = *(const uint4*)(src + (size_t)r * CH + g * 8);
        }
    }

    // Group wc's source rows for tile T start at T*128 + wc*64
    const __half* Bg = Bm + ((size_t)b * NN + wc * 64) * CH;
    const uint32_t bBuf0 = sb + FSM_B + (uint32_t)(wc * 2) * 17408;
    const uint32_t bBuf1 = bBuf0 + 17408;
    const uint32_t vBuf0 = sb + FSM_V + (uint32_t)(wc * 2) * 512;
    const uint32_t vBuf1 = vBuf0 + 512;

    prefetch_half(bBuf0, Bg, tl);
    if (MODE == 1 && tl < 32) {
        const float* s = (tl < 16) ? (vsrc + vbase + wc * 64 + tl * 4)
                                   : (vsrc + vbase + NN + wc * 64 + (tl - 16) * 4);
        CP16(vBuf0 + ((tl < 16) ? tl * 16 : 256 + (tl - 16) * 16), s);
    }
    CP_COMMIT();

    const int g8 = (lane >> 3) & 1, g16 = lane >> 4, l7 = lane & 7, tid4 = lane & 3;
    const uint32_t aB0 = sb + FSM_A + (uint32_t)(((wq * 32 + l7 + g8 * 8) * RS + g16 * 8) * 2);
    const uint32_t aB1 = aB0 + (uint32_t)(16 * RS * 2);
    const uint32_t bOff = (uint32_t)(((wk * 32 + l7 + g16 * 8) * RS + g8 * 8) * 2);

    // Tile-0 halves + sA ready (block-wide once)
    CP_WAIT0();
    __syncthreads();

    // Hoist the a0 row-block fragments (loop-invariant; 32 regs)
    uint32_t aF0[8][4];
    #pragma unroll
    for (int k = 0; k < 8; k++) ldsm4(aF0[k], aB0 + k * 32);

    // Prefetch tile 1 into buf1 (per group)
    prefetch_half(bBuf1, Bg + (size_t)128 * CH, tl);
    if (MODE == 1 && tl < 32) {
        const float* s = (tl < 16) ? (vsrc + vbase + 128 + wc * 64 + tl * 4)
                                   : (vsrc + vbase + NN + 128 + wc * 64 + (tl - 16) * 4);
        CP16(vBuf1 + ((tl < 16) ? tl * 16 : 256 + (tl - 16) * 16), s);
    }
    CP_COMMIT();

    float L[2][2], AX[2][2], AY[2][2];
    #pragma unroll
    for (int rb = 0; rb < 2; rb++)
        #pragma unroll
        for (int h = 0; h < 2; h++) { L[rb][h] = 0.f; AX[rb][h] = 0.f; AY[rb][h] = 0.f; }

    for (int tile = 0; tile < NN / 128; tile++) {
        const uint32_t cur = tile & 1;
        if (tile > 0) {
            CP_WAIT0();                    // this tile's half ready
            GBAR(1 + wc);                  // group done reading buf being refilled
            if (tile + 1 < NN / 128) {
                const int mn = (tile + 1) * 128;
                prefetch_half(cur ? bBuf0 : bBuf1, Bg + (size_t)mn * CH, tl);
                if (MODE == 1 && tl < 32) {
                    const float* s = (tl < 16)
                        ? (vsrc + vbase + mn + wc * 64 + tl * 4)
                        : (vsrc + vbase + NN + mn + wc * 64 + (tl - 16) * 4);
                    CP16((cur ? vBuf0 : vBuf1)
                         + ((tl < 16) ? tl * 16 : 256 + (tl - 16) * 16), s);
                }
                CP_COMMIT();
            }
        }

        const uint32_t bB = (cur ? bBuf1 : bBuf0) + bOff;
        const float* sV = (const float*)(smem + ((cur ? vBuf1 : vBuf0) - sb));

        float c[2][4][4];
        #pragma unroll
        for (int rb = 0; rb < 2; rb++)
            #pragma unroll
            for (int j = 0; j < 4; j++)
                #pragma unroll
                for (int q = 0; q < 4; q++) c[rb][j][q] = 0.f;

        #pragma unroll
        for (int k = 0; k < 8; k++) {
            uint32_t a1[4];
            ldsm4(a1, aB1 + k * 32);
            #pragma unroll
            for (int j2 = 0; j2 < 2; j2++) {
                uint32_t bb[4];
                ldsm4(bb, bB + j2 * (16 * RS * 2) + k * 32);
                mma16816(c[0][j2 * 2],     aF0[k], bb);
                mma16816(c[0][j2 * 2 + 1], aF0[k], bb + 2);
                mma16816(c[1][j2 * 2],     a1, bb);
                mma16816(c[1][j2 * 2 + 1], a1, bb + 2);
            }
        }

        #pragma unroll
        for (int rb = 0; rb < 2; rb++) {
            float Lt0 = 0.f, Lt1 = 0.f;
            #pragma unroll
            for (int j = 0; j < 4; j++) {
                float p0 = ex2f(c[rb][j][0]);
                float p1 = ex2f(c[rb][j][1]);
                float p2 = ex2f(c[rb][j][2]);
                float p3 = ex2f(c[rb][j][3]);
                if (MODE == 0) {
                    float vx0 = (float)(wk * 32 + j * 8 + tid4 * 2);  // m & 63
                    float vx1 = vx0 + 1.f;
                    Lt0 += p0 + p1;  Lt1 += p2 + p3;
                    AX[rb][0] += p0 * vx0 + p1 * vx1;
                    AX[rb][1] += p2 * vx0 + p3 * vx1;
                } else {
                    int cl = wk * 32 + j * 8 + tid4 * 2;              // within half
                    float2 x2 = *(const float2*)&sV[cl];
                    float2 y2 = *(const float2*)&sV[64 + cl];
                    L[rb][0]  += p0 + p1;          L[rb][1]  += p2 + p3;
                    AX[rb][0] += p0 * x2.x + p1 * x2.y;
                    AX[rb][1] += p2 * x2.x + p3 * x2.y;
                    AY[rb][0] += p0 * y2.x + p1 * y2.y;
                    AY[rb][1] += p2 * y2.x + p3 * y2.y;
                }
            }
            if (MODE == 0) {
                float vy = (float)(2 * tile + wc);                    // m >> 6
                L[rb][0] += Lt0;  L[rb][1] += Lt1;
                AY[rb][0] += vy * Lt0;  AY[rb][1] += vy * Lt1;
            }
        }
    }

    #pragma unroll
    for (int o = 1; o <= 2; o <<= 1)
        #pragma unroll
        for (int rb = 0; rb < 2; rb++)
            #pragma unroll
            for (int h = 0; h < 2; h++) {
                L[rb][h]  += __shfl_xor_sync(0xffffffffu, L[rb][h],  o);
                AX[rb][h] += __shfl_xor_sync(0xffffffffu, AX[rb][h], o);
                AY[rb][h] += __shfl_xor_sync(0xffffffffu, AY[rb][h], o);
            }

    // Cross-warp reduction: 4 partials per row (wc x wk); slot 0 combines.
    float* red = (float*)(smem + FSM_RED);
    const int slot = wc * 2 + wk;   // 0..3
    __syncthreads();                // all groups out of the mainloop
    if (slot != 0 && tid4 == 0) {
        #pragma unroll
        for (int rb = 0; rb < 2; rb++)
            #pragma unroll
            for (int h = 0; h < 2; h++) {
                int rl = wq * 32 + rb * 16 + h * 8 + (lane >> 2);
                float* rs = red + (slot - 1) * 192;
                rs[rl]       = L[rb][h];
                rs[64 + rl]  = AX[rb][h];
                rs[128 + rl] = AY[rb][h];
            }
    }
    __syncthreads();
    if (slot == 0 && tid4 == 0) {
        float* ob = out + vbase;
        #pragma unroll
        for (int rb = 0; rb < 2; rb++)
            #pragma unroll
            for (int h = 0; h < 2; h++) {
                int rl = wq * 32 + rb * 16 + h * 8 + (lane >> 2);
                float Lt  = L[rb][h]  + red[rl]       + red[192 + rl]       + red[384 + rl];
                float AXt = AX[rb][h] + red[64 + rl]  + red[192 + 64 + rl]  + red[384 + 64 + rl];
                float AYt = AY[rb][h] + red[128 + rl] + red[192 + 128 + rl] + red[384 + 128 + rl];
                int n = n0 + rl;
                float fx = AXt / Lt, fy = AYt / Lt;
                if (MODE == 0) { fx -= (float)(n & (WW - 1)); fy -= (float)(n >> 6); }
                ob[n] = fx;  ob[NN + n] = fy;
            }
    }
}

// ---------------------------------------------------------------------------
// Proj body (unchanged R8): 128-row tile; q kept in regs as GEMM2 A-fragments.
// ---------------------------------------------------------------------------
__device__ __forceinline__ void proj_body(
    const __half* __restrict__ F0, const float* __restrict__ qw,
    const float* __restrict__ qb,  const float* __restrict__ kw,
    const float* __restrict__ kb,
    __half* __restrict__ QH, __half* __restrict__ KH,
    int b, int n0, char* smem)
{
    __half* sF = (__half*)(smem + PSM_F);
    __half* sW = (__half*)(smem + PSM_W);
    float* qbS = (float*)(smem + PSM_QB);
    float* kbS = (float*)(smem + PSM_KB);
    const uint32_t sbF = smem_u32(sF), sbW = smem_u32(sW);

    const int t = threadIdx.x, wid = t >> 5, lane = t & 31;

    {
        const __half* src = F0 + ((size_t)b * NN + n0) * CH;
        #pragma unroll
        for (int it = 0; it < 8; it++) {
            int idx = it * 256 + t;
            int r = idx >> 4, g = idx & 15;
            *(uint4*)(sF + r * RS + g * 8) = *(const uint4*)(src + (size_t)r * CH + g * 8);
        }
    }
    #pragma unroll
    for (int it = 0; it < 16; it++) {
        int idx = it * 256 + t;
        int r = idx >> 5, g = idx & 31;
        float4 w = *(const float4*)(qw + (size_t)r * CH + g * 4);
        __half h[4] = {__float2half(w.x), __float2half(w.y), __float2half(w.z), __float2half(w.w)};
        *(uint2*)(sW + r * RS + g * 4) = *(uint2*)h;
    }
    if (t < 128) { qbS[t] = qb[t]; kbS[t] = kb[t]; }
    __syncthreads();

    const int g8 = (lane >> 3) & 1, g16 = lane >> 4, l7 = lane & 7, tid4 = lane & 3;
    const uint32_t aBase = sbF + (uint32_t)(((wid * 16 + l7 + g8 * 8) * RS + g16 * 8) * 2);
    const uint32_t bBase = sbW + (uint32_t)(((l7 + g16 * 8) * RS + g8 * 8) * 2);

    float c[16][4];
    #pragma unroll
    for (int j = 0; j < 16; j++)
        #pragma unroll
        for (int q = 0; q < 4; q++) c[j][q] = 0.f;
    #pragma unroll
    for (int k = 0; k < 8; k++) {
        uint32_t a[4];
        ldsm4(a, aBase + k * 32);
        #pragma unroll
        for (int j2 = 0; j2 < 8; j2++) {
            uint32_t bb[4];
            ldsm4(bb, bBase + j2 * (16 * RS * 2) + k * 32);
            mma16816(c[2 * j2],     a, bb);
            mma16816(c[2 * j2 + 1], a, bb + 2);
        }
    }

    uint32_t hq[16][2];
    const int r0 = wid * 16 + (lane >> 2);
    #pragma unroll
    for (int j = 0; j < 16; j++) {
        int col = j * 8 + tid4 * 2;
        float b0 = qbS[col], b1 = qbS[col + 1];
        __half2 v0 = __floats2half2_rn(c[j][0] + b0, c[j][1] + b1);
        __half2 v1 = __floats2half2_rn(c[j][2] + b0, c[j][3] + b1);
        hq[j][0] = *(uint32_t*)&v0;
        hq[j][1] = *(uint32_t*)&v1;
        *(uint32_t*)(QH + ((size_t)b * NN + n0 + r0) * CH + col)     = hq[j][0];
        *(uint32_t*)(QH + ((size_t)b * NN + n0 + r0 + 8) * CH + col) = hq[j][1];
    }

    __syncthreads();
    #pragma unroll
    for (int it = 0; it < 16; it++) {
        int idx = it * 256 + t;
        int r = idx >> 5, g = idx & 31;
        float4 w = *(const float4*)(kw + (size_t)r * CH + g * 4);
        __half h[4] = {__float2half(w.x), __float2half(w.y), __float2half(w.z), __float2half(w.w)};
        *(uint2*)(sW + r * RS + g * 4) = *(uint2*)h;
    }
    __syncthreads();

    float c2[16][4];
    #pragma unroll
    for (int j = 0; j < 16; j++)
        #pragma unroll
        for (int q = 0; q < 4; q++) c2[j][q] = 0.f;
    #pragma unroll
    for (int kk = 0; kk < 8; kk++) {
        uint32_t a[4] = { hq[2 * kk][0], hq[2 * kk][1], hq[2 * kk + 1][0], hq[2 * kk + 1][1] };
        #pragma unroll
        for (int j2 = 0; j2 < 8; j2++) {
            uint32_t bb[4];
            ldsm4(bb, bBase + j2 * (16 * RS * 2) + kk * 32);
            mma16816(c2[2 * j2],     a, bb);
            mma16816(c2[2 * j2 + 1], a, bb + 2);
        }
    }
    #pragma unroll
    for (int j = 0; j < 16; j++) {
        int col = j * 8 + tid4 * 2;
        float b0 = kbS[col], b1 = kbS[col + 1];
        __half2 v0 = __floats2half2_rn((c2[j][0] + b0) * S2F, (c2[j][1] + b1) * S2F);
        __half2 v1 = __floats2half2_rn((c2[j][2] + b0) * S2F, (c2[j][3] + b1) * S2F);
        *(uint32_t*)(KH + ((size_t)b * NN + n0 + r0) * CH + col)     = *(uint32_t*)&v0;
        *(uint32_t*)(KH + ((size_t)b * NN + n0 + r0 + 8) * CH + col) = *(uint32_t*)&v1;
    }
}

// ---------------------------------------------------------------------------
// Fused pipeline kernel (R10 grid): 960 CTAs in bid order:
//   bid   0..191 : proj   (b = idx/24, n0 = (idx%24)*128)  -> g_done[b] += 1
//   bid 192..575 : flash0 (b = idx/48, n0 = (idx%48)*64)   -> g_done[b] += 1
//   bid 576..959 : flash1 — spins until g_done[b] == 72.
// g_done[] zeroed by the conv kernel preceding this launch.
// ---------------------------------------------------------------------------
__global__ void __launch_bounds__(256, 2) fused_kernel(
    const __half* __restrict__ f0h, const __half* __restrict__ f1h,
    const float* __restrict__ qw, const float* __restrict__ qb,
    const float* __restrict__ kw, const float* __restrict__ kb,
    __half* __restrict__ qh, __half* __restrict__ kh,
    float* __restrict__ flow_pred, float* __restrict__ flow)
{
    extern __shared__ char smem[];
    const int bid = blockIdx.x;

    if (bid < 192) {
        const int idx = bid, b = idx / 24;
        proj_body(f0h, qw, qb, kw, kb, qh, kh, b, (idx % 24) * 128, smem);
        __threadfence();
        __syncthreads();
        if (threadIdx.x == 0) atomicAdd(&g_done[b], 1);
    } else if (bid < 576) {
        const int idx = bid - 192, b = idx / 48;
        flash_body<0>(f0h, f1h, nullptr, flow_pred, b, (idx % 48) * 64, smem);
        __threadfence();
        __syncthreads();
        if (threadIdx.x == 0) atomicAdd(&g_done[b], 1);
    } else {
        const int idx = bid - 576, b = idx / 48;
        if (threadIdx.x == 0) {
            while (atomicAdd(&g_done[b], 0) < 72) __nanosleep(200);
            __threadfence();
        }
        __syncthreads();
        flash_body<1>(qh, kh, flow_pred, flow, b, (idx % 48) * 64, smem);
    }
}

// ---------------------------------------------------------------------------
// Fused transpose+convert (re-zeroes g_done): z<8 f0->f0h (x1), z>=8 f1 (xS2)
// ---------------------------------------------------------------------------
__global__ void __launch_bounds__(256) convH2_kernel(
    const float* __restrict__ f0, const float* __restrict__ f1,
    __half* __restrict__ o0, __half* __restrict__ o1)
{
    __shared__ float tile[32][33];
    if (blockIdx.x == 0 && blockIdx.y == 0 && blockIdx.z == 0 &&
        threadIdx.x < BATCH && threadIdx.y == 0)
        g_done[threadIdx.x] = 0;

    const int z = blockIdx.z, b = z & 7;
    const float* in = (z < 8) ? f0 : f1;
    __half* out = (z < 8) ? o0 : o1;
    const float scale = (z < 8) ? 1.0f : S2F;
    const int n0 = blockIdx.x * 32, c0 = blockIdx.y * 32;
    const int tx = threadIdx.x, ty = threadIdx.y;

    const float* ip = in + ((size_t)b * CH + c0) * NN + n0;
    #pragma unroll
    for (int i = 0; i < 4; i++) {
        int c = ty + i * 8;
        tile[c][tx] = ip[(size_t)c * NN + tx];
    }
    __syncthreads();
    __half* op = out + ((size_t)b * NN + n0) * CH + c0;
    #pragma unroll
    for (int i = 0; i < 4; i++) {
        int nr = ty + i * 8;
        op[(size_t)nr * CH + tx] = __float2half(tile[tx][nr] * scale);
    }
}

extern "C" void kernel_launch(void* const* d_in, const int* in_sizes, int n_in,
                              void* d_out, int out_size)
{
    const float* f0 = (const float*)d_in[0];
    const float* f1 = (const float*)d_in[1];
    const float* qw = (const float*)d_in[2];
    const float* qb = (const float*)d_in[3];
    const float* kw = (const float*)d_in[4];
    const float* kb = (const float*)d_in[5];

    float* out       = (float*)d_out;
    float* flow      = out;
    float* flow_pred = out + (size_t)BATCH * 2 * NN;

    void* p;
    cudaGetSymbolAddress(&p, g_f0h); __half* f0h = (__half*)p;
    cudaGetSymbolAddress(&p, g_f1h); __half* f1h = (__half*)p;
    cudaGetSymbolAddress(&p, g_qh);  __half* qh  = (__half*)p;
    cudaGetSymbolAddress(&p, g_kh);  __half* kh  = (__half*)p;

    cudaFuncSetAttribute(fused_kernel, cudaFuncAttributeMaxDynamicSharedMemorySize, FSM_TOT);

    dim3 cgrid(NN / 32, CH / 32, 2 * BATCH);
    dim3 cblk(32, 8);

    convH2_kernel<<<cgrid, cblk>>>(f0, f1, f0h, f1h);
    fused_kernel<<<960, 256, FSM_TOT>>>(f0h, f1h, qw, qb, kw, kb, qh, kh,
                                        flow_pred, flow);
}

// round 17
// speedup vs baseline: 1.1195x; 1.0021x over previous
#include <cuda_runtime.h>
#include <cuda_fp16.h>
#include <cstdint>

#define BATCH 8
#define CH    128
#define HH    48
#define WW    64
#define NN    (HH*WW)   // 3072

#define S2F ((float)(1.4426950408889634 * 0.088388347648318447))

__device__ __half g_f0h[BATCH*NN*CH];
__device__ __half g_f1h[BATCH*NN*CH];
__device__ __half g_qh [BATCH*NN*CH];
__device__ __half g_kh [BATCH*NN*CH];
// [0..7]  = conv completions per batch (target 24: 2 tensors x 12 chunks)
// [8..15] = stage0 (proj+flash0) completions per batch (target 72)
__device__ int    g_done[16];

__device__ __forceinline__ uint32_t smem_u32(const void* p) {
    uint32_t a;
    asm("{ .reg .u64 t; cvta.to.shared.u64 t, %1; cvt.u32.u64 %0, t; }" : "=r"(a) : "l"(p));
    return a;
}
__device__ __forceinline__ void ldsm4(uint32_t* r, uint32_t addr) {
    asm volatile("ldmatrix.sync.aligned.m8n8.x4.shared.b16 {%0,%1,%2,%3}, [%4];"
        : "=r"(r[0]), "=r"(r[1]), "=r"(r[2]), "=r"(r[3]) : "r"(addr));
}
__device__ __forceinline__ void mma16816(float* c, const uint32_t* a, const uint32_t* b) {
    asm volatile("mma.sync.aligned.m16n8k16.row.col.f32.f16.f16.f32 "
        "{%0,%1,%2,%3}, {%4,%5,%6,%7}, {%8,%9}, {%0,%1,%2,%3};"
        : "+f"(c[0]), "+f"(c[1]), "+f"(c[2]), "+f"(c[3])
        : "r"(a[0]), "r"(a[1]), "r"(a[2]), "r"(a[3]), "r"(b[0]), "r"(b[1]));
}
__device__ __forceinline__ float ex2f(float x) {
    float y; asm("ex2.approx.f32 %0, %1;" : "=f"(y) : "f"(x)); return y;
}
#define CP16(dst, src) asm volatile("cp.async.cg.shared.global [%0], [%1], 16;" :: "r"(dst), "l"(src))
#define CP_COMMIT()    asm volatile("cp.async.commit_group;" ::: "memory")
#define CP_WAIT0()     asm volatile("cp.async.wait_group 0;" ::: "memory")
#define GBAR(id)       asm volatile("bar.sync %0, 128;" :: "r"(id) : "memory")

#define RS 136

// Flash smem: 64-query A tile + per-group double-buffered 64-key B half-tiles
#define FSM_A    0          // 17408
#define FSM_B    17408      // 4 x 17408 (group g, buf c at g*2+c) -> ends 87040
#define FSM_V    87040      // 4 x 512
#define FSM_RED  89088      // 576 floats (3 partial sets x 192)
#define FSM_TOT  91648

// Proj smem map (fits inside FSM_TOT)
#define PSM_F   0
#define PSM_W   34816
#define PSM_QB  69632
#define PSM_KB  70144

// 64-row half-tile prefetch by one 128-thread group (tl = t & 127)
__device__ __forceinline__ void prefetch_half(uint32_t dstBase, const __half* src, int tl) {
    #pragma unroll
    for (int it = 0; it < 8; it++) {
        int idx = it * 128 + tl;
        int r = idx >> 4, g = idx & 15;
        CP16(dstBase + (uint32_t)((r * RS + g * 8) * 2), src + (size_t)r * CH + g * 8);
    }
}

// ---------------------------------------------------------------------------
// Flash body (R15, unchanged math): 64q tile, 24 key tiles of 128; two
// independent key-half pipelines (wc); 32q x 32k warp tiles; a0 hoisted.
// NOTE: A/Bm/vsrc are plain const pointers (no __restrict__) because the
// underlying buffers are written earlier in the SAME kernel launch by other
// CTAs — must not allow ld.global.nc.
// ---------------------------------------------------------------------------
template<int MODE>
__device__ __forceinline__ void flash_body(
    const __half* A, const __half* Bm,
    const float* vsrc, float* out,
    int b, int n0, char* smem)
{
    const uint32_t sb = smem_u32(smem);
    const int t = threadIdx.x, wid = t >> 5, lane = t & 31;
    const int wc = wid >> 2;
    const int wq = (wid >> 1) & 1;
    const int wk = wid & 1;
    const int tl = t & 127;
    const size_t vbase = (size_t)b * 2 * NN;

    {   // query tile: 64 rows
        __half* sA = (__half*)smem;
        const __half* src = A + ((size_t)b * NN + n0) * CH;
        #pragma unroll
        for (int it = 0; it < 4; it++) {
            int idx = it * 256 + t;
            int r = idx >> 4, g = idx & 15;
            *(uint4*)(sA + r * RS + g * 8) = *(const uint4*)(src + (size_t)r * CH + g * 8);
        }
    }

    const __half* Bg = Bm + ((size_t)b * NN + wc * 64) * CH;
    const uint32_t bBuf0 = sb + FSM_B + (uint32_t)(wc * 2) * 17408;
    const uint32_t bBuf1 = bBuf0 + 17408;
    const uint32_t vBuf0 = sb + FSM_V + (uint32_t)(wc * 2) * 512;
    const uint32_t vBuf1 = vBuf0 + 512;

    prefetch_half(bBuf0, Bg, tl);
    if (MODE == 1 && tl < 32) {
        const float* s = (tl < 16) ? (vsrc + vbase + wc * 64 + tl * 4)
                                   : (vsrc + vbase + NN + wc * 64 + (tl - 16) * 4);
        CP16(vBuf0 + ((tl < 16) ? tl * 16 : 256 + (tl - 16) * 16), s);
    }
    CP_COMMIT();

    const int g8 = (lane >> 3) & 1, g16 = lane >> 4, l7 = lane & 7, tid4 = lane & 3;
    const uint32_t aB0 = sb + FSM_A + (uint32_t)(((wq * 32 + l7 + g8 * 8) * RS + g16 * 8) * 2);
    const uint32_t aB1 = aB0 + (uint32_t)(16 * RS * 2);
    const uint32_t bOff = (uint32_t)(((wk * 32 + l7 + g16 * 8) * RS + g8 * 8) * 2);

    CP_WAIT0();
    __syncthreads();

    uint32_t aF0[8][4];
    #pragma unroll
    for (int k = 0; k < 8; k++) ldsm4(aF0[k], aB0 + k * 32);

    prefetch_half(bBuf1, Bg + (size_t)128 * CH, tl);
    if (MODE == 1 && tl < 32) {
        const float* s = (tl < 16) ? (vsrc + vbase + 128 + wc * 64 + tl * 4)
                                   : (vsrc + vbase + NN + 128 + wc * 64 + (tl - 16) * 4);
        CP16(vBuf1 + ((tl < 16) ? tl * 16 : 256 + (tl - 16) * 16), s);
    }
    CP_COMMIT();

    float L[2][2], AX[2][2], AY[2][2];
    #pragma unroll
    for (int rb = 0; rb < 2; rb++)
        #pragma unroll
        for (int h = 0; h < 2; h++) { L[rb][h] = 0.f; AX[rb][h] = 0.f; AY[rb][h] = 0.f; }

    for (int tile = 0; tile < NN / 128; tile++) {
        const uint32_t cur = tile & 1;
        if (tile > 0) {
            CP_WAIT0();
            GBAR(1 + wc);
            if (tile + 1 < NN / 128) {
                const int mn = (tile + 1) * 128;
                prefetch_half(cur ? bBuf0 : bBuf1, Bg + (size_t)mn * CH, tl);
                if (MODE == 1 && tl < 32) {
                    const float* s = (tl < 16)
                        ? (vsrc + vbase + mn + wc * 64 + tl * 4)
                        : (vsrc + vbase + NN + mn + wc * 64 + (tl - 16) * 4);
                    CP16((cur ? vBuf0 : vBuf1)
                         + ((tl < 16) ? tl * 16 : 256 + (tl - 16) * 16), s);
                }
                CP_COMMIT();
            }
        }

        const uint32_t bB = (cur ? bBuf1 : bBuf0) + bOff;
        const float* sV = (const float*)(smem + ((cur ? vBuf1 : vBuf0) - sb));

        float c[2][4][4];
        #pragma unroll
        for (int rb = 0; rb < 2; rb++)
            #pragma unroll
            for (int j = 0; j < 4; j++)
                #pragma unroll
                for (int q = 0; q < 4; q++) c[rb][j][q] = 0.f;

        #pragma unroll
        for (int k = 0; k < 8; k++) {
            uint32_t a1[4];
            ldsm4(a1, aB1 + k * 32);
            #pragma unroll
            for (int j2 = 0; j2 < 2; j2++) {
                uint32_t bb[4];
                ldsm4(bb, bB + j2 * (16 * RS * 2) + k * 32);
                mma16816(c[0][j2 * 2],     aF0[k], bb);
                mma16816(c[0][j2 * 2 + 1], aF0[k], bb + 2);
                mma16816(c[1][j2 * 2],     a1, bb);
                mma16816(c[1][j2 * 2 + 1], a1, bb + 2);
            }
        }

        #pragma unroll
        for (int rb = 0; rb < 2; rb++) {
            float Lt0 = 0.f, Lt1 = 0.f;
            #pragma unroll
            for (int j = 0; j < 4; j++) {
                float p0 = ex2f(c[rb][j][0]);
                float p1 = ex2f(c[rb][j][1]);
                float p2 = ex2f(c[rb][j][2]);
                float p3 = ex2f(c[rb][j][3]);
                if (MODE == 0) {
                    float vx0 = (float)(wk * 32 + j * 8 + tid4 * 2);
                    float vx1 = vx0 + 1.f;
                    Lt0 += p0 + p1;  Lt1 += p2 + p3;
                    AX[rb][0] += p0 * vx0 + p1 * vx1;
                    AX[rb][1] += p2 * vx0 + p3 * vx1;
                } else {
                    int cl = wk * 32 + j * 8 + tid4 * 2;
                    float2 x2 = *(const float2*)&sV[cl];
                    float2 y2 = *(const float2*)&sV[64 + cl];
                    L[rb][0]  += p0 + p1;          L[rb][1]  += p2 + p3;
                    AX[rb][0] += p0 * x2.x + p1 * x2.y;
                    AX[rb][1] += p2 * x2.x + p3 * x2.y;
                    AY[rb][0] += p0 * y2.x + p1 * y2.y;
                    AY[rb][1] += p2 * y2.x + p3 * y2.y;
                }
            }
            if (MODE == 0) {
                float vy = (float)(2 * tile + wc);
                L[rb][0] += Lt0;  L[rb][1] += Lt1;
                AY[rb][0] += vy * Lt0;  AY[rb][1] += vy * Lt1;
            }
        }
    }

    #pragma unroll
    for (int o = 1; o <= 2; o <<= 1)
        #pragma unroll
        for (int rb = 0; rb < 2; rb++)
            #pragma unroll
            for (int h = 0; h < 2; h++) {
                L[rb][h]  += __shfl_xor_sync(0xffffffffu, L[rb][h],  o);
                AX[rb][h] += __shfl_xor_sync(0xffffffffu, AX[rb][h], o);
                AY[rb][h] += __shfl_xor_sync(0xffffffffu, AY[rb][h], o);
            }

    float* red = (float*)(smem + FSM_RED);
    const int slot = wc * 2 + wk;
    __syncthreads();
    if (slot != 0 && tid4 == 0) {
        #pragma unroll
        for (int rb = 0; rb < 2; rb++)
            #pragma unroll
            for (int h = 0; h < 2; h++) {
                int rl = wq * 32 + rb * 16 + h * 8 + (lane >> 2);
                float* rs = red + (slot - 1) * 192;
                rs[rl]       = L[rb][h];
                rs[64 + rl]  = AX[rb][h];
                rs[128 + rl] = AY[rb][h];
            }
    }
    __syncthreads();
    if (slot == 0 && tid4 == 0) {
        float* ob = out + vbase;
        #pragma unroll
        for (int rb = 0; rb < 2; rb++)
            #pragma unroll
            for (int h = 0; h < 2; h++) {
                int rl = wq * 32 + rb * 16 + h * 8 + (lane >> 2);
                float Lt  = L[rb][h]  + red[rl]       + red[192 + rl]       + red[384 + rl];
                float AXt = AX[rb][h] + red[64 + rl]  + red[192 + 64 + rl]  + red[384 + 64 + rl];
                float AYt = AY[rb][h] + red[128 + rl] + red[192 + 128 + rl] + red[384 + 128 + rl];
                int n = n0 + rl;
                float fx = AXt / Lt, fy = AYt / Lt;
                if (MODE == 0) { fx -= (float)(n & (WW - 1)); fy -= (float)(n >> 6); }
                ob[n] = fx;  ob[NN + n] = fy;
            }
    }
}

// ---------------------------------------------------------------------------
// Proj body (R8 math, plain pointers): 128-row tile; q in regs for GEMM2.
// ---------------------------------------------------------------------------
__device__ __forceinline__ void proj_body(
    const __half* F0, const float* __restrict__ qw,
    const float* __restrict__ qb,  const float* __restrict__ kw,
    const float* __restrict__ kb,
    __half* QH, __half* KH,
    int b, int n0, char* smem)
{
    __half* sF = (__half*)(smem + PSM_F);
    __half* sW = (__half*)(smem + PSM_W);
    float* qbS = (float*)(smem + PSM_QB);
    float* kbS = (float*)(smem + PSM_KB);
    const uint32_t sbF = smem_u32(sF), sbW = smem_u32(sW);

    const int t = threadIdx.x, wid = t >> 5, lane = t & 31;

    {
        const __half* src = F0 + ((size_t)b * NN + n0) * CH;
        #pragma unroll
        for (int it = 0; it < 8; it++) {
            int idx = it * 256 + t;
            int r = idx >> 4, g = idx & 15;
            *(uint4*)(sF + r * RS + g * 8) = *(const uint4*)(src + (size_t)r * CH + g * 8);
        }
    }
    #pragma unroll
    for (int it = 0; it < 16; it++) {
        int idx = it * 256 + t;
        int r = idx >> 5, g = idx & 31;
        float4 w = *(const float4*)(qw + (size_t)r * CH + g * 4);
        __half h[4] = {__float2half(w.x), __float2half(w.y), __float2half(w.z), __float2half(w.w)};
        *(uint2*)(sW + r * RS + g * 4) = *(uint2*)h;
    }
    if (t < 128) { qbS[t] = qb[t]; kbS[t] = kb[t]; }
    __syncthreads();

    const int g8 = (lane >> 3) & 1, g16 = lane >> 4, l7 = lane & 7, tid4 = lane & 3;
    const uint32_t aBase = sbF + (uint32_t)(((wid * 16 + l7 + g8 * 8) * RS + g16 * 8) * 2);
    const uint32_t bBase = sbW + (uint32_t)(((l7 + g16 * 8) * RS + g8 * 8) * 2);

    float c[16][4];
    #pragma unroll
    for (int j = 0; j < 16; j++)
        #pragma unroll
        for (int q = 0; q < 4; q++) c[j][q] = 0.f;
    #pragma unroll
    for (int k = 0; k < 8; k++) {
        uint32_t a[4];
        ldsm4(a, aBase + k * 32);
        #pragma unroll
        for (int j2 = 0; j2 < 8; j2++) {
            uint32_t bb[4];
            ldsm4(bb, bBase + j2 * (16 * RS * 2) + k * 32);
            mma16816(c[2 * j2],     a, bb);
            mma16816(c[2 * j2 + 1], a, bb + 2);
        }
    }

    uint32_t hq[16][2];
    const int r0 = wid * 16 + (lane >> 2);
    #pragma unroll
    for (int j = 0; j < 16; j++) {
        int col = j * 8 + tid4 * 2;
        float b0 = qbS[col], b1 = qbS[col + 1];
        __half2 v0 = __floats2half2_rn(c[j][0] + b0, c[j][1] + b1);
        __half2 v1 = __floats2half2_rn(c[j][2] + b0, c[j][3] + b1);
        hq[j][0] = *(uint32_t*)&v0;
        hq[j][1] = *(uint32_t*)&v1;
        *(uint32_t*)(QH + ((size_t)b * NN + n0 + r0) * CH + col)     = hq[j][0];
        *(uint32_t*)(QH + ((size_t)b * NN + n0 + r0 + 8) * CH + col) = hq[j][1];
    }

    __syncthreads();
    #pragma unroll
    for (int it = 0; it < 16; it++) {
        int idx = it * 256 + t;
        int r = idx >> 5, g = idx & 31;
        float4 w = *(const float4*)(kw + (size_t)r * CH + g * 4);
        __half h[4] = {__float2half(w.x), __float2half(w.y), __float2half(w.z), __float2half(w.w)};
        *(uint2*)(sW + r * RS + g * 4) = *(uint2*)h;
    }
    __syncthreads();

    float c2[16][4];
    #pragma unroll
    for (int j = 0; j < 16; j++)
        #pragma unroll
        for (int q = 0; q < 4; q++) c2[j][q] = 0.f;
    #pragma unroll
    for (int kk = 0; kk < 8; kk++) {
        uint32_t a[4] = { hq[2 * kk][0], hq[2 * kk][1], hq[2 * kk + 1][0], hq[2 * kk + 1][1] };
        #pragma unroll
        for (int j2 = 0; j2 < 8; j2++) {
            uint32_t bb[4];
            ldsm4(bb, bBase + j2 * (16 * RS * 2) + kk * 32);
            mma16816(c2[2 * j2],     a, bb);
            mma16816(c2[2 * j2 + 1], a, bb + 2);
        }
    }
    #pragma unroll
    for (int j = 0; j < 16; j++) {
        int col = j * 8 + tid4 * 2;
        float b0 = kbS[col], b1 = kbS[col + 1];
        __half2 v0 = __floats2half2_rn((c2[j][0] + b0) * S2F, (c2[j][1] + b1) * S2F);
        __half2 v1 = __floats2half2_rn((c2[j][2] + b0) * S2F, (c2[j][3] + b1) * S2F);
        *(uint32_t*)(KH + ((size_t)b * NN + n0 + r0) * CH + col)     = *(uint32_t*)&v0;
        *(uint32_t*)(KH + ((size_t)b * NN + n0 + r0 + 8) * CH + col) = *(uint32_t*)&v1;
    }
}

// ---------------------------------------------------------------------------
// Conv body: transpose+convert one 256-row chunk of one (b, tensor):
// fp32 [C][N] -> fp16 [N][C] (x scale). Stores are __half2 (coalesced).
// ---------------------------------------------------------------------------
__device__ __forceinline__ void conv_body(
    const float* in, __half* out, float scale,
    int b, int chunk_n0, char* smem)
{
    float (*tile)[33] = (float(*)[33])smem;   // [64][33] floats
    const int tx = threadIdx.x & 31, ty = threadIdx.x >> 5;  // 32 x 8

    #pragma unroll 1
    for (int rep = 0; rep < 8; rep++) {
        const int n0 = chunk_n0 + rep * 32;
        #pragma unroll 1
        for (int c0 = 0; c0 < CH; c0 += 64) {
            __syncthreads();   // previous pass's reads done
            const float* ip = in + ((size_t)b * CH + c0) * NN + n0;
            #pragma unroll
            for (int i = 0; i < 8; i++) {
                int c = ty + i * 8;
                tile[c][tx] = ip[(size_t)c * NN + tx];
            }
            __syncthreads();
            __half* op = out + ((size_t)b * NN + n0) * CH + c0;
            #pragma unroll
            for (int i = 0; i < 4; i++) {
                int nr = ty + i * 8;
                __half2 v = __floats2half2_rn(tile[tx * 2][nr] * scale,
                                              tile[tx * 2 + 1][nr] * scale);
                *(__half2*)(op + (size_t)nr * CH + tx * 2) = v;
            }
        }
    }
}

// ---------------------------------------------------------------------------
// Mega-kernel: 1152 CTAs, bid order conv -> proj -> flash0 -> flash1.
// Scratch buffers passed ONCE each, non-const (no ld.global.nc possible).
//   bid    0..191 : conv   -> g_done[b] += 1      (target 24)
//   bid  192..383 : proj   — waits g_done[b]==24; -> g_done[8+b] += 1
//   bid  384..767 : flash0 — waits g_done[b]==24; -> g_done[8+b] += 1
//   bid  768..1151: flash1 — waits g_done[8+b]==72.
// ---------------------------------------------------------------------------
__global__ void __launch_bounds__(256, 2) fused_kernel(
    const float* __restrict__ f0, const float* __restrict__ f1,
    const float* __restrict__ qw, const float* __restrict__ qb,
    const float* __restrict__ kw, const float* __restrict__ kb,
    __half* f0h, __half* f1h, __half* qh, __half* kh,
    float* flow_pred, float* flow)
{
    extern __shared__ char smem[];
    const int bid = blockIdx.x;

    if (bid < 192) {
        const int idx = bid, b = idx / 24, r = idx % 24;
        if (r < 12) conv_body(f0, f0h, 1.0f, b, r * 256, smem);
        else        conv_body(f1, f1h, S2F,  b, (r - 12) * 256, smem);
        __threadfence();
        __syncthreads();
        if (threadIdx.x == 0) atomicAdd(&g_done[b], 1);
    } else if (bid < 384) {
        const int idx = bid - 192, b = idx / 24;
        if (threadIdx.x == 0) {
            while (atomicAdd(&g_done[b], 0) < 24) __nanosleep(200);
            __threadfence();
        }
        __syncthreads();
        proj_body(f0h, qw, qb, kw, kb, qh, kh, b, (idx % 24) * 128, smem);
        __threadfence();
        __syncthreads();
        if (threadIdx.x == 0) atomicAdd(&g_done[8 + b], 1);
    } else if (bid < 768) {
        const int idx = bid - 384, b = idx / 48;
        if (threadIdx.x == 0) {
            while (atomicAdd(&g_done[b], 0) < 24) __nanosleep(200);
            __threadfence();
        }
        __syncthreads();
        flash_body<0>(f0h, f1h, nullptr, flow_pred, b, (idx % 48) * 64, smem);
        __threadfence();
        __syncthreads();
        if (threadIdx.x == 0) atomicAdd(&g_done[8 + b], 1);
    } else {
        const int idx = bid - 768, b = idx / 48;
        if (threadIdx.x == 0) {
            while (atomicAdd(&g_done[8 + b], 0) < 72) __nanosleep(200);
            __threadfence();
        }
        __syncthreads();
        flash_body<1>(qh, kh, flow_pred, flow, b, (idx % 48) * 64, smem);
    }
}

extern "C" void kernel_launch(void* const* d_in, const int* in_sizes, int n_in,
                              void* d_out, int out_size)
{
    const float* f0 = (const float*)d_in[0];
    const float* f1 = (const float*)d_in[1];
    const float* qw = (const float*)d_in[2];
    const float* qb = (const float*)d_in[3];
    const float* kw = (const float*)d_in[4];
    const float* kb = (const float*)d_in[5];

    float* out       = (float*)d_out;
    float* flow      = out;
    float* flow_pred = out + (size_t)BATCH * 2 * NN;

    void* p;
    cudaGetSymbolAddress(&p, g_f0h); __half* f0h = (__half*)p;
    cudaGetSymbolAddress(&p, g_f1h); __half* f1h = (__half*)p;
    cudaGetSymbolAddress(&p, g_qh);  __half* qh  = (__half*)p;
    cudaGetSymbolAddress(&p, g_kh);  __half* kh  = (__half*)p;
    void* dn; cudaGetSymbolAddress(&dn, g_done);

    cudaFuncSetAttribute(fused_kernel, cudaFuncAttributeMaxDynamicSharedMemorySize, FSM_TOT);

    cudaMemsetAsync(dn, 0, 16 * sizeof(int));
    fused_kernel<<<1152, 256, FSM_TOT>>>(f0, f1, qw, qb, kw, kb,
                                         f0h, f1h, qh, kh, flow_pred, flow);
}